// round 5
// baseline (speedup 1.0000x reference)
#include <cuda_runtime.h>
#include <cuda_bf16.h>
#include <math.h>
#include <float.h>

#define NPTS 2048
#define KNN  10
#define OUTF 256

// _rn intrinsics: immune to --use_fast_math; used on all eigen/kNN-critical math
#define FMUL(a,b)  __fmul_rn((a),(b))
#define FADD(a,b)  __fadd_rn((a),(b))
#define FSUB(a,b)  __fsub_rn((a),(b))
#define FDIV(a,b)  __fdiv_rn((a),(b))
#define FSQRT(a)   __fsqrt_rn((a))

__device__ float g_normals[NPTS * 3];

// ---------------------------------------------------------------------------
// LAPACK fp32 building blocks (netlib-faithful, LAPACK >= 3.10 conventions)
// ---------------------------------------------------------------------------

__device__ __forceinline__ float f_sign(float a, float b) {
    // Fortran SIGN(a,b): |a| with the sign of b; b==+0 -> +|a|
    return (b >= 0.f) ? fabsf(a) : -fabsf(a);
}

__device__ __forceinline__ float slapy2f(float x, float y) {
    float xa = fabsf(x), ya = fabsf(y);
    float w = fmaxf(xa, ya), z = fminf(xa, ya);
    if (z == 0.f) return w;
    float t = FDIV(z, w);
    return FMUL(w, FSQRT(FADD(1.f, FMUL(t, t))));
}

// LAPACK 3.10+ slartg: c >= 0 always
__device__ __forceinline__ void slartgf(float f, float g, float* c, float* s, float* r) {
    if (g == 0.f)      { *c = 1.f; *s = 0.f; *r = f; }
    else if (f == 0.f) { *c = 0.f; *s = (g >= 0.f) ? 1.f : -1.f; *r = fabsf(g); }
    else {
        float d  = FSQRT(FADD(FMUL(f, f), FMUL(g, g)));
        float rr = (f >= 0.f) ? d : -d;     // sign(d, f)
        *c = FDIV(fabsf(f), d);
        *s = FDIV(g, rr);
        *r = rr;
    }
}

__device__ void slaev2f(float a, float b, float c,
                        float* rt1, float* rt2, float* cs1, float* sn1) {
    float sm  = FADD(a, c);
    float df  = FSUB(a, c);
    float adf = fabsf(df);
    float tb  = FADD(b, b);
    float ab  = fabsf(tb);
    float acmx, acmn;
    if (fabsf(a) > fabsf(c)) { acmx = a; acmn = c; } else { acmx = c; acmn = a; }
    float rt;
    if (adf > ab) {
        float t = FDIV(ab, adf);
        rt = FMUL(adf, FSQRT(FADD(1.f, FMUL(t, t))));
    } else if (adf < ab) {
        float t = FDIV(adf, ab);
        rt = FMUL(ab, FSQRT(FADD(1.f, FMUL(t, t))));
    } else {
        rt = FMUL(ab, FSQRT(2.f));
    }
    int sgn1;
    if (sm < 0.f) {
        *rt1 = FMUL(0.5f, FSUB(sm, rt)); sgn1 = -1;
        *rt2 = FSUB(FMUL(FDIV(acmx, *rt1), acmn), FMUL(FDIV(b, *rt1), b));
    } else if (sm > 0.f) {
        *rt1 = FMUL(0.5f, FADD(sm, rt)); sgn1 = 1;
        *rt2 = FSUB(FMUL(FDIV(acmx, *rt1), acmn), FMUL(FDIV(b, *rt1), b));
    } else {
        *rt1 = FMUL(0.5f, rt); *rt2 = FMUL(-0.5f, rt); sgn1 = 1;
    }
    float cs; int sgn2;
    if (df >= 0.f) { cs = FADD(df, rt); sgn2 =  1; }
    else           { cs = FSUB(df, rt); sgn2 = -1; }
    float acs = fabsf(cs);
    if (acs > ab) {
        float ct = FDIV(-tb, cs);
        *sn1 = FDIV(1.f, FSQRT(FADD(1.f, FMUL(ct, ct))));
        *cs1 = FMUL(ct, *sn1);
    } else {
        if (ab == 0.f) { *cs1 = 1.f; *sn1 = 0.f; }
        else {
            float tn = FDIV(-cs, tb);
            *cs1 = FDIV(1.f, FSQRT(FADD(1.f, FMUL(tn, tn))));
            *sn1 = FMUL(tn, *cs1);
        }
    }
    if (sgn1 == sgn2) { float tn = *cs1; *cs1 = -(*sn1); *sn1 = tn; }
}

// slasr 'R','V','B': rotate columns of 3x3 z (col-major), block starting at
// Fortran column `lcol`, mm columns; rotation j uses wc/ws[lcol-1 + j-1].
__device__ void slasr_b(float* z, int lcol, int mm, const float* wc, const float* ws) {
    for (int j = mm - 1; j >= 1; --j) {
        float c = wc[lcol - 2 + j], s = ws[lcol - 2 + j];
        if (c != 1.f || s != 0.f) {
            int ca = lcol + j - 1;  // 0-based higher column
            int cb = ca - 1;
            #pragma unroll
            for (int r = 0; r < 3; ++r) {
                float temp = z[ca * 3 + r];
                z[ca * 3 + r] = FSUB(FMUL(c, temp), FMUL(s, z[cb * 3 + r]));
                z[cb * 3 + r] = FADD(FMUL(s, temp), FMUL(c, z[cb * 3 + r]));
            }
        }
    }
}
__device__ void slasr_f(float* z, int lcol, int mm, const float* wc, const float* ws) {
    for (int j = 1; j <= mm - 1; ++j) {
        float c = wc[lcol - 2 + j], s = ws[lcol - 2 + j];
        if (c != 1.f || s != 0.f) {
            int ca = lcol + j - 1;
            int cb = ca - 1;
            #pragma unroll
            for (int r = 0; r < 3; ++r) {
                float temp = z[ca * 3 + r];
                z[ca * 3 + r] = FSUB(FMUL(c, temp), FMUL(s, z[cb * 3 + r]));
                z[cb * 3 + r] = FADD(FMUL(s, temp), FMUL(c, z[cb * 3 + r]));
            }
        }
    }
}

// ssteqr('I', n=3): eigen-decomposition of tridiagonal (d, e), z accumulates
// rotations from identity. Faithful control-flow translation of netlib ssteqr.
__device__ void ssteqr3(float* d, float* e, float* z) {
    const float eps    = 5.9604645e-8f;     // slamch('E') fp32
    const float eps2   = eps * eps;
    const float safmin = 1.17549435e-38f;   // slamch('S')
    float wc[2], ws[2];
    int l1, l, lsv, lend, lendsv, m, i, jtot, nmaxit;
    float p, g, r, s, c, f, bb, rt1, rt2, anorm, tst;
    nmaxit = 90; jtot = 0; l1 = 1;

L10:
    if (l1 > 3) goto L160;
    if (l1 > 1) e[l1 - 2] = 0.f;
    if (l1 <= 2) {
        for (m = l1; m <= 2; ++m) {
            tst = fabsf(e[m - 1]);
            if (tst == 0.f) goto L30;
            if (tst <= FMUL(FMUL(FSQRT(fabsf(d[m - 1])), FSQRT(fabsf(d[m]))), eps)) {
                e[m - 1] = 0.f; goto L30;
            }
        }
    }
    m = 3;
L30:
    l = l1; lsv = l; lend = m; lendsv = lend; l1 = m + 1;
    if (lend == l) goto L10;
    anorm = 0.f;
    for (i = l; i <= lend; ++i)     anorm = fmaxf(anorm, fabsf(d[i - 1]));
    for (i = l; i <= lend - 1; ++i) anorm = fmaxf(anorm, fabsf(e[i - 1]));
    if (anorm == 0.f) goto L10;
    // (no slascl scaling: covariance magnitudes are well inside [ssfmin, ssfmax])
    if (fabsf(d[lend - 1]) < fabsf(d[l - 1])) { lend = lsv; l = lendsv; }
    if (lend > l) goto L40; else goto L90;

    // ---------------- QL iteration ----------------
L40:
    if (l != lend) {
        for (m = l; m <= lend - 1; ++m) {
            tst = FMUL(e[m - 1], e[m - 1]);
            if (tst <= FADD(FMUL(FMUL(eps2, fabsf(d[m - 1])), fabsf(d[m])), safmin)) goto L60;
        }
    }
    m = lend;
L60:
    if (m < lend) e[m - 1] = 0.f;
    p = d[l - 1];
    if (m == l) goto L80;
    if (m == l + 1) {
        slaev2f(d[l - 1], e[l - 1], d[l], &rt1, &rt2, &c, &s);
        wc[l - 1] = c; ws[l - 1] = s;
        slasr_b(z, l, 2, wc, ws);
        d[l - 1] = rt1; d[l] = rt2; e[l - 1] = 0.f;
        l += 2;
        if (l <= lend) goto L40;
        goto L140;
    }
    if (jtot == nmaxit) goto L140;
    jtot++;
    g = FDIV(FSUB(d[l], p), FMUL(2.f, e[l - 1]));
    r = slapy2f(g, 1.f);
    g = FADD(FSUB(d[m - 1], p), FDIV(e[l - 1], FADD(g, f_sign(r, g))));
    s = 1.f; c = 1.f; p = 0.f;
    for (i = m - 1; i >= l; --i) {
        f  = FMUL(s, e[i - 1]);
        bb = FMUL(c, e[i - 1]);
        slartgf(g, f, &c, &s, &r);
        if (i != m - 1) e[i] = r;
        g = FSUB(d[i], p);
        r = FADD(FMUL(FSUB(d[i - 1], g), s), FMUL(FMUL(2.f, c), bb));
        p = FMUL(s, r);
        d[i] = FADD(g, p);
        g = FSUB(FMUL(c, r), bb);
        wc[i - 1] = c; ws[i - 1] = -s;
    }
    slasr_b(z, l, m - l + 1, wc, ws);
    d[l - 1] = FSUB(d[l - 1], p);
    e[l - 1] = g;
    goto L40;
L80:
    d[l - 1] = p;
    l++;
    if (l <= lend) goto L40;
    goto L140;

    // ---------------- QR iteration ----------------
L90:
    if (l != lend) {
        for (m = l; m >= lend + 1; --m) {
            tst = FMUL(e[m - 2], e[m - 2]);
            if (tst <= FADD(FMUL(FMUL(eps2, fabsf(d[m - 1])), fabsf(d[m - 2])), safmin)) goto L110;
        }
    }
    m = lend;
L110:
    if (m > lend) e[m - 2] = 0.f;
    p = d[l - 1];
    if (m == l) goto L130;
    if (m == l - 1) {
        slaev2f(d[l - 2], e[l - 2], d[l - 1], &rt1, &rt2, &c, &s);
        wc[m - 1] = c; ws[m - 1] = s;
        slasr_f(z, l - 1, 2, wc, ws);
        d[l - 2] = rt1; d[l - 1] = rt2; e[l - 2] = 0.f;
        l -= 2;
        if (l >= lend) goto L90;
        goto L140;
    }
    if (jtot == nmaxit) goto L140;
    jtot++;
    g = FDIV(FSUB(d[l - 2], p), FMUL(2.f, e[l - 2]));
    r = slapy2f(g, 1.f);
    g = FADD(FSUB(d[m - 1], p), FDIV(e[l - 2], FADD(g, f_sign(r, g))));
    s = 1.f; c = 1.f; p = 0.f;
    for (i = m; i <= l - 1; ++i) {
        f  = FMUL(s, e[i - 1]);
        bb = FMUL(c, e[i - 1]);
        slartgf(g, f, &c, &s, &r);
        if (i != m) e[i - 2] = r;
        g = FSUB(d[i - 1], p);
        r = FADD(FMUL(FSUB(d[i], g), s), FMUL(FMUL(2.f, c), bb));
        p = FMUL(s, r);
        d[i - 1] = FADD(g, p);
        g = FSUB(FMUL(c, r), bb);
        wc[i - 1] = c; ws[i - 1] = s;
    }
    slasr_f(z, m, l - m + 1, wc, ws);
    d[l - 1] = FSUB(d[l - 1], p);
    e[l - 2] = g;
    goto L90;
L130:
    d[l - 1] = p;
    l--;
    if (l >= lend) goto L90;
    goto L140;

L140:
    if (jtot < nmaxit) goto L10;
    goto L160;   // non-convergence (cannot happen for 3x3 well-scaled)

L160:
    // selection sort ascending, swapping eigenvector columns
    for (int ii = 2; ii <= 3; ++ii) {
        int ia = ii - 1, k = ia;
        float pp = d[ia - 1];
        for (int j = ii; j <= 3; ++j)
            if (d[j - 1] < pp) { k = j; pp = d[j - 1]; }
        if (k != ia) {
            d[k - 1] = d[ia - 1]; d[ia - 1] = pp;
            #pragma unroll
            for (int rr2 = 0; rr2 < 3; ++rr2) {
                float t = z[(ia - 1) * 3 + rr2];
                z[(ia - 1) * 3 + rr2] = z[(k - 1) * 3 + rr2];
                z[(k - 1) * 3 + rr2] = t;
            }
        }
    }
}

// Full ssyevd path for the 3x3 symmetric matrix (lower triangle given):
// ssytd2 (uplo='L') -> ssteqr('I') -> apply Householder (sormtr), return
// eigenvector of the SMALLEST eigenvalue in nrm[3].
__device__ void smallest_eigvec3(float a11, float a21, float a31,
                                 float a22, float a32, float a33,
                                 float* nrm) {
    // --- ssytd2, n=3, uplo='L': one reflector on A(2:3,1) ---
    float alpha = a21;
    float xnorm = fabsf(a31);
    float tau1, v3, e1;
    if (xnorm == 0.f) {
        tau1 = 0.f; e1 = alpha; v3 = 0.f;
    } else {
        float beta = -f_sign(slapy2f(alpha, xnorm), alpha);
        tau1 = FDIV(FSUB(beta, alpha), beta);
        v3   = FMUL(a31, FDIV(1.f, FSUB(alpha, beta)));   // sscal by 1/(alpha-beta)
        e1   = beta;
    }
    if (tau1 != 0.f) {
        // v = (1, v3); B = [[a22, a32],[a32, a33]] (symmetric)
        float x1 = FMUL(tau1, FADD(a22, FMUL(a32, v3)));
        float x2 = FMUL(tau1, FADD(a32, FMUL(a33, v3)));
        float al = FMUL(FMUL(-0.5f, tau1), FADD(x1, FMUL(x2, v3)));
        float w1 = FADD(x1, al);
        float w2 = FADD(x2, FMUL(al, v3));
        a22 = FSUB(a22, FMUL(2.f, w1));
        a32 = FSUB(a32, FADD(FMUL(v3, w1), w2));
        a33 = FSUB(a33, FMUL(2.f, FMUL(v3, w2)));
    }
    float d[3] = {a11, a22, a33};
    float e[2] = {e1, a32};
    float z[9] = {1.f, 0.f, 0.f, 0.f, 1.f, 0.f, 0.f, 0.f, 1.f};  // col-major I

    ssteqr3(d, e, z);

    // sormtr('L','L','N'): apply H(1) = I - tau*v*v^T to rows 2:3 of column 0
    float z0 = z[0], z1 = z[1], z2 = z[2];
    if (tau1 != 0.f) {
        float t = FMUL(tau1, FADD(z1, FMUL(v3, z2)));
        z1 = FSUB(z1, t);
        z2 = FSUB(z2, FMUL(t, v3));
    }
    nrm[0] = z0; nrm[1] = z1; nrm[2] = z2;
}

// ---------------------------------------------------------------------------
// Kernel 1: brute-force stable kNN + covariance + smallest eigenvector
// ---------------------------------------------------------------------------
__global__ void __launch_bounds__(256)
knn_normals_kernel(const float* __restrict__ pts, float* __restrict__ normals) {
    __shared__ float sx[NPTS], sy[NPTS], sz[NPTS];
    int tid = threadIdx.x;
    for (int j = tid; j < NPTS; j += 256) {
        sx[j] = pts[j * 3 + 0];
        sy[j] = pts[j * 3 + 1];
        sz[j] = pts[j * 3 + 2];
    }
    __syncthreads();

    int i = blockIdx.x * 256 + tid;
    if (i >= NPTS) return;
    float pix = sx[i], piy = sy[i], piz = sz[i];

    // stable 11-smallest (self included at slot 0, distance exactly 0)
    float bv[KNN + 1];
    int   bi[KNN + 1];
    #pragma unroll
    for (int q = 0; q <= KNN; ++q) { bv[q] = FLT_MAX; bi[q] = -1; }

    for (int j = 0; j < NPTS; ++j) {
        float dx = FSUB(pix, sx[j]);
        float dy = FSUB(piy, sy[j]);
        float dz = FSUB(piz, sz[j]);
        float sq = FADD(FADD(FMUL(dx, dx), FMUL(dy, dy)), FMUL(dz, dz));
        if (sq < bv[KNN]) {
            int pos = KNN;
            while (pos > 0 && bv[pos - 1] > sq) {   // strict >: stable (ties keep lower j first)
                bv[pos] = bv[pos - 1]; bi[pos] = bi[pos - 1]; --pos;
            }
            bv[pos] = sq; bi[pos] = j;
        }
    }

    // neighbors = bi[1..10] (slot 0 is self); mean over neighbors
    float nx[KNN], ny[KNN], nz[KNN];
    float mx = 0.f, my = 0.f, mz = 0.f;
    #pragma unroll
    for (int k = 0; k < KNN; ++k) {
        int j = bi[k + 1];
        nx[k] = sx[j]; ny[k] = sy[j]; nz[k] = sz[j];
        mx = FADD(mx, nx[k]); my = FADD(my, ny[k]); mz = FADD(mz, nz[k]);
    }
    mx = FDIV(mx, 10.f); my = FDIV(my, 10.f); mz = FDIV(mz, 10.f);

    // covariance (lower triangle), sum over k then /10
    float c00 = 0.f, c10 = 0.f, c20 = 0.f, c11 = 0.f, c21 = 0.f, c22 = 0.f;
    #pragma unroll
    for (int k = 0; k < KNN; ++k) {
        float cx = FSUB(nx[k], mx);
        float cy = FSUB(ny[k], my);
        float cz = FSUB(nz[k], mz);
        c00 = FADD(c00, FMUL(cx, cx));
        c10 = FADD(c10, FMUL(cy, cx));
        c20 = FADD(c20, FMUL(cz, cx));
        c11 = FADD(c11, FMUL(cy, cy));
        c21 = FADD(c21, FMUL(cz, cy));
        c22 = FADD(c22, FMUL(cz, cz));
    }
    c00 = FDIV(c00, 10.f); c10 = FDIV(c10, 10.f); c20 = FDIV(c20, 10.f);
    c11 = FDIV(c11, 10.f); c21 = FDIV(c21, 10.f); c22 = FDIV(c22, 10.f);

    float nrm[3];
    smallest_eigvec3(c00, c10, c20, c11, c21, c22, nrm);
    normals[i * 3 + 0] = nrm[0];
    normals[i * 3 + 1] = nrm[1];
    normals[i * 3 + 2] = nrm[2];
}

// ---------------------------------------------------------------------------
// Kernel 2: PPF mean over j (block per point i) + 4->256 linear layer
// ---------------------------------------------------------------------------
__global__ void __launch_bounds__(256)
ppf_kernel(const float* __restrict__ pts, const float* __restrict__ normals,
           const float* __restrict__ W, const float* __restrict__ b,
           float* __restrict__ out) {
    __shared__ float sx[NPTS], sy[NPTS], sz[NPTS], snx[NPTS], sny[NPTS], snz[NPTS];
    int tid = threadIdx.x;
    for (int j = tid; j < NPTS; j += 256) {
        sx[j]  = pts[j * 3 + 0];
        sy[j]  = pts[j * 3 + 1];
        sz[j]  = pts[j * 3 + 2];
        snx[j] = normals[j * 3 + 0];
        sny[j] = normals[j * 3 + 1];
        snz[j] = normals[j * 3 + 2];
    }
    __syncthreads();

    int i = blockIdx.x;
    float pix = sx[i],  piy = sy[i],  piz = sz[i];
    float nix = snx[i], niy = sny[i], niz = snz[i];

    float s0 = 0.f, s1 = 0.f, s2 = 0.f, s3 = 0.f;
    for (int j = tid; j < NPTS; j += 256) {
        float dx = pix - sx[j], dy = piy - sy[j], dz = piz - sz[j];
        float njx = snx[j], njy = sny[j], njz = snz[j];

        float sq = dx * dx + dy * dy + dz * dz;
        float dn = (sq > 0.f) ? sqrtf(sq) : 0.f;

        // angle(ni, d)
        float cx = niy * dz - niz * dy;
        float cy = niz * dx - nix * dz;
        float cz = nix * dy - niy * dx;
        float csq = cx * cx + cy * cy + cz * cz;
        float cn  = (csq > 0.f) ? sqrtf(csq) : 0.f;
        float dot = nix * dx + niy * dy + niz * dz;
        float a1 = atan2f(cn, dot);

        // angle(nj, d)
        cx = njy * dz - njz * dy;
        cy = njz * dx - njx * dz;
        cz = njx * dy - njy * dx;
        csq = cx * cx + cy * cy + cz * cz;
        cn  = (csq > 0.f) ? sqrtf(csq) : 0.f;
        dot = njx * dx + njy * dy + njz * dz;
        float a2 = atan2f(cn, dot);

        // angle(ni, nj)
        cx = niy * njz - niz * njy;
        cy = niz * njx - nix * njz;
        cz = nix * njy - niy * njx;
        csq = cx * cx + cy * cy + cz * cz;
        cn  = (csq > 0.f) ? sqrtf(csq) : 0.f;
        dot = nix * njx + niy * njy + niz * njz;
        float a3 = atan2f(cn, dot);

        s0 += dn; s1 += a1; s2 += a2; s3 += a3;
    }

    // block reduction of the 4 sums (reuse sx[] as scratch after sync)
    #pragma unroll
    for (int off = 16; off > 0; off >>= 1) {
        s0 += __shfl_down_sync(0xFFFFFFFFu, s0, off);
        s1 += __shfl_down_sync(0xFFFFFFFFu, s1, off);
        s2 += __shfl_down_sync(0xFFFFFFFFu, s2, off);
        s3 += __shfl_down_sync(0xFFFFFFFFu, s3, off);
    }
    int w = tid >> 5, lane = tid & 31;
    __syncthreads();               // everyone done reading smem
    if (lane == 0) {
        sx[w * 4 + 0] = s0; sx[w * 4 + 1] = s1;
        sx[w * 4 + 2] = s2; sx[w * 4 + 3] = s3;
    }
    __syncthreads();
    if (tid == 0) {
        float t0 = 0.f, t1 = 0.f, t2 = 0.f, t3 = 0.f;
        #pragma unroll
        for (int q = 0; q < 8; ++q) {
            t0 += sx[q * 4 + 0]; t1 += sx[q * 4 + 1];
            t2 += sx[q * 4 + 2]; t3 += sx[q * 4 + 3];
        }
        sx[0] = t0 / 2048.f; sx[1] = t1 / 2048.f;
        sx[2] = t2 / 2048.f; sx[3] = t3 / 2048.f;
    }
    __syncthreads();
    float f0 = sx[0], f1 = sx[1], f2 = sx[2], f3 = sx[3];

    // one output feature per thread: s[t] = feat . W[t,:] + b[t]
    float acc = f0 * W[tid * 4 + 0];
    acc = acc + f1 * W[tid * 4 + 1];
    acc = acc + f2 * W[tid * 4 + 2];
    acc = acc + f3 * W[tid * 4 + 3];
    acc = acc + b[tid];
    out[i * OUTF + tid] = acc;
}

extern "C" void kernel_launch(void* const* d_in, const int* in_sizes, int n_in,
                              void* d_out, int out_size) {
    const float* points = (const float*)d_in[0];   // (1, 2048, 3)
    const float* W      = (const float*)d_in[1];   // (256, 4)
    const float* b      = (const float*)d_in[2];   // (256,)
    float* out          = (float*)d_out;           // (1, 2048, 256)
    (void)in_sizes; (void)n_in; (void)out_size;

    float* normals;
    cudaGetSymbolAddress((void**)&normals, g_normals);

    knn_normals_kernel<<<NPTS / 256, 256>>>(points, normals);
    ppf_kernel<<<NPTS, 256>>>(points, normals, W, b, out);
}

// round 6
// speedup vs baseline: 4.8830x; 4.8830x over previous
#include <cuda_runtime.h>
#include <cuda_bf16.h>
#include <math.h>
#include <float.h>

#define NPTS 2048
#define KNN  10
#define OUTF 256

// _rn intrinsics: immune to compiler fast-math; used on all eigen/kNN-critical math
#define FMUL(a,b)  __fmul_rn((a),(b))
#define FADD(a,b)  __fadd_rn((a),(b))
#define FSUB(a,b)  __fsub_rn((a),(b))
#define FDIV(a,b)  __fdiv_rn((a),(b))
#define FSQRT(a)   __fsqrt_rn((a))

__device__ float g_normals[NPTS * 3];

// ---------------------------------------------------------------------------
// LAPACK fp32 building blocks (netlib-faithful, LAPACK >= 3.10 conventions)
// ---------------------------------------------------------------------------

__device__ __forceinline__ float f_sign(float a, float b) {
    return (b >= 0.f) ? fabsf(a) : -fabsf(a);
}

__device__ __forceinline__ float slapy2f(float x, float y) {
    float xa = fabsf(x), ya = fabsf(y);
    float w = fmaxf(xa, ya), z = fminf(xa, ya);
    if (z == 0.f) return w;
    float t = FDIV(z, w);
    return FMUL(w, FSQRT(FADD(1.f, FMUL(t, t))));
}

// LAPACK 3.10+ slartg: c >= 0 always
__device__ __forceinline__ void slartgf(float f, float g, float* c, float* s, float* r) {
    if (g == 0.f)      { *c = 1.f; *s = 0.f; *r = f; }
    else if (f == 0.f) { *c = 0.f; *s = (g >= 0.f) ? 1.f : -1.f; *r = fabsf(g); }
    else {
        float d  = FSQRT(FADD(FMUL(f, f), FMUL(g, g)));
        float rr = (f >= 0.f) ? d : -d;
        *c = FDIV(fabsf(f), d);
        *s = FDIV(g, rr);
        *r = rr;
    }
}

__device__ void slaev2f(float a, float b, float c,
                        float* rt1, float* rt2, float* cs1, float* sn1) {
    float sm  = FADD(a, c);
    float df  = FSUB(a, c);
    float adf = fabsf(df);
    float tb  = FADD(b, b);
    float ab  = fabsf(tb);
    float acmx, acmn;
    if (fabsf(a) > fabsf(c)) { acmx = a; acmn = c; } else { acmx = c; acmn = a; }
    float rt;
    if (adf > ab) {
        float t = FDIV(ab, adf);
        rt = FMUL(adf, FSQRT(FADD(1.f, FMUL(t, t))));
    } else if (adf < ab) {
        float t = FDIV(adf, ab);
        rt = FMUL(ab, FSQRT(FADD(1.f, FMUL(t, t))));
    } else {
        rt = FMUL(ab, FSQRT(2.f));
    }
    int sgn1;
    if (sm < 0.f) {
        *rt1 = FMUL(0.5f, FSUB(sm, rt)); sgn1 = -1;
        *rt2 = FSUB(FMUL(FDIV(acmx, *rt1), acmn), FMUL(FDIV(b, *rt1), b));
    } else if (sm > 0.f) {
        *rt1 = FMUL(0.5f, FADD(sm, rt)); sgn1 = 1;
        *rt2 = FSUB(FMUL(FDIV(acmx, *rt1), acmn), FMUL(FDIV(b, *rt1), b));
    } else {
        *rt1 = FMUL(0.5f, rt); *rt2 = FMUL(-0.5f, rt); sgn1 = 1;
    }
    float cs; int sgn2;
    if (df >= 0.f) { cs = FADD(df, rt); sgn2 =  1; }
    else           { cs = FSUB(df, rt); sgn2 = -1; }
    float acs = fabsf(cs);
    if (acs > ab) {
        float ct = FDIV(-tb, cs);
        *sn1 = FDIV(1.f, FSQRT(FADD(1.f, FMUL(ct, ct))));
        *cs1 = FMUL(ct, *sn1);
    } else {
        if (ab == 0.f) { *cs1 = 1.f; *sn1 = 0.f; }
        else {
            float tn = FDIV(-cs, tb);
            *cs1 = FDIV(1.f, FSQRT(FADD(1.f, FMUL(tn, tn))));
            *sn1 = FMUL(tn, *cs1);
        }
    }
    if (sgn1 == sgn2) { float tn = *cs1; *cs1 = -(*sn1); *sn1 = tn; }
}

__device__ void slasr_b(float* z, int lcol, int mm, const float* wc, const float* ws) {
    for (int j = mm - 1; j >= 1; --j) {
        float c = wc[lcol - 2 + j], s = ws[lcol - 2 + j];
        if (c != 1.f || s != 0.f) {
            int ca = lcol + j - 1;
            int cb = ca - 1;
            #pragma unroll
            for (int r = 0; r < 3; ++r) {
                float temp = z[ca * 3 + r];
                z[ca * 3 + r] = FSUB(FMUL(c, temp), FMUL(s, z[cb * 3 + r]));
                z[cb * 3 + r] = FADD(FMUL(s, temp), FMUL(c, z[cb * 3 + r]));
            }
        }
    }
}
__device__ void slasr_f(float* z, int lcol, int mm, const float* wc, const float* ws) {
    for (int j = 1; j <= mm - 1; ++j) {
        float c = wc[lcol - 2 + j], s = ws[lcol - 2 + j];
        if (c != 1.f || s != 0.f) {
            int ca = lcol + j - 1;
            int cb = ca - 1;
            #pragma unroll
            for (int r = 0; r < 3; ++r) {
                float temp = z[ca * 3 + r];
                z[ca * 3 + r] = FSUB(FMUL(c, temp), FMUL(s, z[cb * 3 + r]));
                z[cb * 3 + r] = FADD(FMUL(s, temp), FMUL(c, z[cb * 3 + r]));
            }
        }
    }
}

// ssteqr('I', n=3) — faithful control-flow translation of netlib ssteqr
__device__ void ssteqr3(float* d, float* e, float* z) {
    const float eps    = 5.9604645e-8f;
    const float eps2   = eps * eps;
    const float safmin = 1.17549435e-38f;
    float wc[2], ws[2];
    int l1, l, lsv, lend, lendsv, m, i, jtot, nmaxit;
    float p, g, r, s, c, f, bb, rt1, rt2, anorm, tst;
    nmaxit = 90; jtot = 0; l1 = 1;

L10:
    if (l1 > 3) goto L160;
    if (l1 > 1) e[l1 - 2] = 0.f;
    if (l1 <= 2) {
        for (m = l1; m <= 2; ++m) {
            tst = fabsf(e[m - 1]);
            if (tst == 0.f) goto L30;
            if (tst <= FMUL(FMUL(FSQRT(fabsf(d[m - 1])), FSQRT(fabsf(d[m]))), eps)) {
                e[m - 1] = 0.f; goto L30;
            }
        }
    }
    m = 3;
L30:
    l = l1; lsv = l; lend = m; lendsv = lend; l1 = m + 1;
    if (lend == l) goto L10;
    anorm = 0.f;
    for (i = l; i <= lend; ++i)     anorm = fmaxf(anorm, fabsf(d[i - 1]));
    for (i = l; i <= lend - 1; ++i) anorm = fmaxf(anorm, fabsf(e[i - 1]));
    if (anorm == 0.f) goto L10;
    if (fabsf(d[lend - 1]) < fabsf(d[l - 1])) { lend = lsv; l = lendsv; }
    if (lend > l) goto L40; else goto L90;

L40: // QL
    if (l != lend) {
        for (m = l; m <= lend - 1; ++m) {
            tst = FMUL(e[m - 1], e[m - 1]);
            if (tst <= FADD(FMUL(FMUL(eps2, fabsf(d[m - 1])), fabsf(d[m])), safmin)) goto L60;
        }
    }
    m = lend;
L60:
    if (m < lend) e[m - 1] = 0.f;
    p = d[l - 1];
    if (m == l) goto L80;
    if (m == l + 1) {
        slaev2f(d[l - 1], e[l - 1], d[l], &rt1, &rt2, &c, &s);
        wc[l - 1] = c; ws[l - 1] = s;
        slasr_b(z, l, 2, wc, ws);
        d[l - 1] = rt1; d[l] = rt2; e[l - 1] = 0.f;
        l += 2;
        if (l <= lend) goto L40;
        goto L140;
    }
    if (jtot == nmaxit) goto L140;
    jtot++;
    g = FDIV(FSUB(d[l], p), FMUL(2.f, e[l - 1]));
    r = slapy2f(g, 1.f);
    g = FADD(FSUB(d[m - 1], p), FDIV(e[l - 1], FADD(g, f_sign(r, g))));
    s = 1.f; c = 1.f; p = 0.f;
    for (i = m - 1; i >= l; --i) {
        f  = FMUL(s, e[i - 1]);
        bb = FMUL(c, e[i - 1]);
        slartgf(g, f, &c, &s, &r);
        if (i != m - 1) e[i] = r;
        g = FSUB(d[i], p);
        r = FADD(FMUL(FSUB(d[i - 1], g), s), FMUL(FMUL(2.f, c), bb));
        p = FMUL(s, r);
        d[i] = FADD(g, p);
        g = FSUB(FMUL(c, r), bb);
        wc[i - 1] = c; ws[i - 1] = -s;
    }
    slasr_b(z, l, m - l + 1, wc, ws);
    d[l - 1] = FSUB(d[l - 1], p);
    e[l - 1] = g;
    goto L40;
L80:
    d[l - 1] = p;
    l++;
    if (l <= lend) goto L40;
    goto L140;

L90: // QR
    if (l != lend) {
        for (m = l; m >= lend + 1; --m) {
            tst = FMUL(e[m - 2], e[m - 2]);
            if (tst <= FADD(FMUL(FMUL(eps2, fabsf(d[m - 1])), fabsf(d[m - 2])), safmin)) goto L110;
        }
    }
    m = lend;
L110:
    if (m > lend) e[m - 2] = 0.f;
    p = d[l - 1];
    if (m == l) goto L130;
    if (m == l - 1) {
        slaev2f(d[l - 2], e[l - 2], d[l - 1], &rt1, &rt2, &c, &s);
        wc[m - 1] = c; ws[m - 1] = s;
        slasr_f(z, l - 1, 2, wc, ws);
        d[l - 2] = rt1; d[l - 1] = rt2; e[l - 2] = 0.f;
        l -= 2;
        if (l >= lend) goto L90;
        goto L140;
    }
    if (jtot == nmaxit) goto L140;
    jtot++;
    g = FDIV(FSUB(d[l - 2], p), FMUL(2.f, e[l - 2]));
    r = slapy2f(g, 1.f);
    g = FADD(FSUB(d[m - 1], p), FDIV(e[l - 2], FADD(g, f_sign(r, g))));
    s = 1.f; c = 1.f; p = 0.f;
    for (i = m; i <= l - 1; ++i) {
        f  = FMUL(s, e[i - 1]);
        bb = FMUL(c, e[i - 1]);
        slartgf(g, f, &c, &s, &r);
        if (i != m) e[i - 2] = r;
        g = FSUB(d[i - 1], p);
        r = FADD(FMUL(FSUB(d[i], g), s), FMUL(FMUL(2.f, c), bb));
        p = FMUL(s, r);
        d[i - 1] = FADD(g, p);
        g = FSUB(FMUL(c, r), bb);
        wc[i - 1] = c; ws[i - 1] = s;
    }
    slasr_f(z, m, l - m + 1, wc, ws);
    d[l - 1] = FSUB(d[l - 1], p);
    e[l - 2] = g;
    goto L90;
L130:
    d[l - 1] = p;
    l--;
    if (l >= lend) goto L90;
    goto L140;

L140:
    if (jtot < nmaxit) goto L10;
    goto L160;

L160:
    for (int ii = 2; ii <= 3; ++ii) {
        int ia = ii - 1, k = ia;
        float pp = d[ia - 1];
        for (int j = ii; j <= 3; ++j)
            if (d[j - 1] < pp) { k = j; pp = d[j - 1]; }
        if (k != ia) {
            d[k - 1] = d[ia - 1]; d[ia - 1] = pp;
            #pragma unroll
            for (int rr2 = 0; rr2 < 3; ++rr2) {
                float t = z[(ia - 1) * 3 + rr2];
                z[(ia - 1) * 3 + rr2] = z[(k - 1) * 3 + rr2];
                z[(k - 1) * 3 + rr2] = t;
            }
        }
    }
}

__device__ void smallest_eigvec3(float a11, float a21, float a31,
                                 float a22, float a32, float a33,
                                 float* nrm) {
    float alpha = a21;
    float xnorm = fabsf(a31);
    float tau1, v3, e1;
    if (xnorm == 0.f) {
        tau1 = 0.f; e1 = alpha; v3 = 0.f;
    } else {
        float beta = -f_sign(slapy2f(alpha, xnorm), alpha);
        tau1 = FDIV(FSUB(beta, alpha), beta);
        v3   = FMUL(a31, FDIV(1.f, FSUB(alpha, beta)));
        e1   = beta;
    }
    if (tau1 != 0.f) {
        float x1 = FMUL(tau1, FADD(a22, FMUL(a32, v3)));
        float x2 = FMUL(tau1, FADD(a32, FMUL(a33, v3)));
        float al = FMUL(FMUL(-0.5f, tau1), FADD(x1, FMUL(x2, v3)));
        float w1 = FADD(x1, al);
        float w2 = FADD(x2, FMUL(al, v3));
        a22 = FSUB(a22, FMUL(2.f, w1));
        a32 = FSUB(a32, FADD(FMUL(v3, w1), w2));
        a33 = FSUB(a33, FMUL(2.f, FMUL(v3, w2)));
    }
    float d[3] = {a11, a22, a33};
    float e[2] = {e1, a32};
    float z[9] = {1.f, 0.f, 0.f, 0.f, 1.f, 0.f, 0.f, 0.f, 1.f};

    ssteqr3(d, e, z);

    float z0 = z[0], z1 = z[1], z2 = z[2];
    if (tau1 != 0.f) {
        float t = FMUL(tau1, FADD(z1, FMUL(v3, z2)));
        z1 = FSUB(z1, t);
        z2 = FSUB(z2, FMUL(t, v3));
    }
    nrm[0] = z0; nrm[1] = z1; nrm[2] = z2;
}

// ---------------------------------------------------------------------------
// Kernel 1: WARP-PER-POINT kNN + covariance + smallest eigenvector.
// Packed (float-bits(sq) << 32 | idx) keys: u64 order == (sq, idx) lexicographic
// == top_k's stable tie order. Merge of per-lane sorted top-11 lists is exact.
// ---------------------------------------------------------------------------
__global__ void __launch_bounds__(256)
knn_normals_kernel(const float* __restrict__ pts, float* __restrict__ normals) {
    __shared__ float sx[NPTS], sy[NPTS], sz[NPTS];
    int tid = threadIdx.x;
    for (int j = tid; j < NPTS; j += 256) {
        sx[j] = pts[j * 3 + 0];
        sy[j] = pts[j * 3 + 1];
        sz[j] = pts[j * 3 + 2];
    }
    __syncthreads();

    int warp = tid >> 5, lane = tid & 31;
    int i = blockIdx.x * 8 + warp;

    float pix = sx[i], piy = sy[i], piz = sz[i];

    // per-lane sorted top-11 of packed keys
    unsigned long long kv[KNN + 1];
    #pragma unroll
    for (int q = 0; q <= KNN; ++q) kv[q] = 0xFFFFFFFFFFFFFFFFull;
    unsigned long long worst = 0xFFFFFFFFFFFFFFFFull;

    for (int j = lane; j < NPTS; j += 32) {
        float dx = FSUB(pix, sx[j]);
        float dy = FSUB(piy, sy[j]);
        float dz = FSUB(piz, sz[j]);
        float sq = FADD(FADD(FMUL(dx, dx), FMUL(dy, dy)), FMUL(dz, dz));
        unsigned long long key =
            ((unsigned long long)__float_as_uint(sq) << 32) | (unsigned)j;
        if (key < worst) {
            int pos = KNN;
            while (pos > 0 && kv[pos - 1] > key) { kv[pos] = kv[pos - 1]; --pos; }
            kv[pos] = key;
            worst = kv[KNN];
        }
    }

    // 11-round warp merge: global min of remaining heads each round
    int head = 0;
    int nbr[KNN + 1];
    #pragma unroll
    for (int r = 0; r <= KNN; ++r) {
        unsigned long long mykey = (head <= KNN) ? kv[head] : 0xFFFFFFFFFFFFFFFFull;
        unsigned long long m = mykey;
        #pragma unroll
        for (int off = 16; off > 0; off >>= 1) {
            unsigned long long o = __shfl_xor_sync(0xFFFFFFFFu, m, off);
            m = (o < m) ? o : m;
        }
        if (mykey == m) head++;           // unique owner (idx distinct)
        nbr[r] = (int)(unsigned)(m & 0xFFFFFFFFull);
    }

    if (lane == 0) {
        // neighbors = nbr[1..10] (slot 0 dropped, as reference's knn[:,1:])
        float nx[KNN], ny[KNN], nz[KNN];
        float mx = 0.f, my = 0.f, mz = 0.f;
        #pragma unroll
        for (int k = 0; k < KNN; ++k) {
            int j = nbr[k + 1];
            nx[k] = sx[j]; ny[k] = sy[j]; nz[k] = sz[j];
            mx = FADD(mx, nx[k]); my = FADD(my, ny[k]); mz = FADD(mz, nz[k]);
        }
        mx = FDIV(mx, 10.f); my = FDIV(my, 10.f); mz = FDIV(mz, 10.f);

        float c00 = 0.f, c10 = 0.f, c20 = 0.f, c11 = 0.f, c21 = 0.f, c22 = 0.f;
        #pragma unroll
        for (int k = 0; k < KNN; ++k) {
            float cx = FSUB(nx[k], mx);
            float cy = FSUB(ny[k], my);
            float cz = FSUB(nz[k], mz);
            c00 = FADD(c00, FMUL(cx, cx));
            c10 = FADD(c10, FMUL(cy, cx));
            c20 = FADD(c20, FMUL(cz, cx));
            c11 = FADD(c11, FMUL(cy, cy));
            c21 = FADD(c21, FMUL(cz, cy));
            c22 = FADD(c22, FMUL(cz, cz));
        }
        c00 = FDIV(c00, 10.f); c10 = FDIV(c10, 10.f); c20 = FDIV(c20, 10.f);
        c11 = FDIV(c11, 10.f); c21 = FDIV(c21, 10.f); c22 = FDIV(c22, 10.f);

        float nrm[3];
        smallest_eigvec3(c00, c10, c20, c11, c21, c22, nrm);
        normals[i * 3 + 0] = nrm[0];
        normals[i * 3 + 1] = nrm[1];
        normals[i * 3 + 2] = nrm[2];
    }
}

// ---------------------------------------------------------------------------
// Fast atan2 for y >= 0 (result in [0, pi]); cephes atanf coefficients,
// range-reduced to [0, tan(pi/8)], ~1e-7 abs error. Budget: tol 1e-3.
// ---------------------------------------------------------------------------
__device__ __forceinline__ float fast_atan2_pos(float y, float x) {
    const float PI    = 3.14159265358979323846f;
    const float PIO2  = 1.57079632679489661923f;
    const float PIO4  = 0.78539816339744830962f;
    const float TAN8  = 0.41421356237309504880f;

    float ax = fabsf(x);
    float mn = fminf(y, ax), mx = fmaxf(y, ax);
    float t = (mx == 0.f) ? 0.f : __fdividef(mn, mx);

    float add = 0.f;
    if (t > TAN8) { t = __fdividef(t - 1.f, t + 1.f); add = PIO4; }

    float z = t * t;
    float p = 8.05374449538e-2f;
    p = p * z - 1.38776856032e-1f;
    p = p * z + 1.99777106478e-1f;
    p = p * z - 3.33329491539e-1f;
    float r = fmaf(p * z, t, t) + add;

    if (y > ax)  r = PIO2 - r;
    if (x < 0.f) r = PI - r;
    return r;
}

// ---------------------------------------------------------------------------
// Kernel 2: PPF mean over j (block per point i) + 4->256 linear layer
// ---------------------------------------------------------------------------
__global__ void __launch_bounds__(256)
ppf_kernel(const float* __restrict__ pts, const float* __restrict__ normals,
           const float* __restrict__ W, const float* __restrict__ b,
           float* __restrict__ out) {
    __shared__ float sx[NPTS], sy[NPTS], sz[NPTS], snx[NPTS], sny[NPTS], snz[NPTS];
    int tid = threadIdx.x;
    for (int j = tid; j < NPTS; j += 256) {
        sx[j]  = pts[j * 3 + 0];
        sy[j]  = pts[j * 3 + 1];
        sz[j]  = pts[j * 3 + 2];
        snx[j] = normals[j * 3 + 0];
        sny[j] = normals[j * 3 + 1];
        snz[j] = normals[j * 3 + 2];
    }
    __syncthreads();

    int i = blockIdx.x;
    float pix = sx[i],  piy = sy[i],  piz = sz[i];
    float nix = snx[i], niy = sny[i], niz = snz[i];

    float s0 = 0.f, s1 = 0.f, s2 = 0.f, s3 = 0.f;
    #pragma unroll
    for (int jj = 0; jj < NPTS / 256; ++jj) {
        int j = tid + jj * 256;
        float dx = pix - sx[j], dy = piy - sy[j], dz = piz - sz[j];
        float njx = snx[j], njy = sny[j], njz = snz[j];

        float sq = dx * dx + dy * dy + dz * dz;
        float dn = (sq > 0.f) ? sq * rsqrtf(sq) : 0.f;

        // angle(ni, d)
        float cx = niy * dz - niz * dy;
        float cy = niz * dx - nix * dz;
        float cz = nix * dy - niy * dx;
        float csq = cx * cx + cy * cy + cz * cz;
        float cn  = (csq > 0.f) ? csq * rsqrtf(csq) : 0.f;
        float dot = nix * dx + niy * dy + niz * dz;
        float a1 = fast_atan2_pos(cn, dot);

        // angle(nj, d)
        cx = njy * dz - njz * dy;
        cy = njz * dx - njx * dz;
        cz = njx * dy - njy * dx;
        csq = cx * cx + cy * cy + cz * cz;
        cn  = (csq > 0.f) ? csq * rsqrtf(csq) : 0.f;
        dot = njx * dx + njy * dy + njz * dz;
        float a2 = fast_atan2_pos(cn, dot);

        // angle(ni, nj)
        cx = niy * njz - niz * njy;
        cy = niz * njx - nix * njz;
        cz = nix * njy - niy * njx;
        csq = cx * cx + cy * cy + cz * cz;
        cn  = (csq > 0.f) ? csq * rsqrtf(csq) : 0.f;
        dot = nix * njx + niy * njy + niz * njz;
        float a3 = fast_atan2_pos(cn, dot);

        s0 += dn; s1 += a1; s2 += a2; s3 += a3;
    }

    #pragma unroll
    for (int off = 16; off > 0; off >>= 1) {
        s0 += __shfl_down_sync(0xFFFFFFFFu, s0, off);
        s1 += __shfl_down_sync(0xFFFFFFFFu, s1, off);
        s2 += __shfl_down_sync(0xFFFFFFFFu, s2, off);
        s3 += __shfl_down_sync(0xFFFFFFFFu, s3, off);
    }
    int w = tid >> 5, lane = tid & 31;
    __syncthreads();
    if (lane == 0) {
        sx[w * 4 + 0] = s0; sx[w * 4 + 1] = s1;
        sx[w * 4 + 2] = s2; sx[w * 4 + 3] = s3;
    }
    __syncthreads();
    if (tid == 0) {
        float t0 = 0.f, t1 = 0.f, t2 = 0.f, t3 = 0.f;
        #pragma unroll
        for (int q = 0; q < 8; ++q) {
            t0 += sx[q * 4 + 0]; t1 += sx[q * 4 + 1];
            t2 += sx[q * 4 + 2]; t3 += sx[q * 4 + 3];
        }
        sx[0] = t0 / 2048.f; sx[1] = t1 / 2048.f;
        sx[2] = t2 / 2048.f; sx[3] = t3 / 2048.f;
    }
    __syncthreads();
    float f0 = sx[0], f1 = sx[1], f2 = sx[2], f3 = sx[3];

    float acc = f0 * W[tid * 4 + 0];
    acc = acc + f1 * W[tid * 4 + 1];
    acc = acc + f2 * W[tid * 4 + 2];
    acc = acc + f3 * W[tid * 4 + 3];
    acc = acc + b[tid];
    out[i * OUTF + tid] = acc;
}

extern "C" void kernel_launch(void* const* d_in, const int* in_sizes, int n_in,
                              void* d_out, int out_size) {
    const float* points = (const float*)d_in[0];   // (1, 2048, 3)
    const float* W      = (const float*)d_in[1];   // (256, 4)
    const float* b      = (const float*)d_in[2];   // (256,)
    float* out          = (float*)d_out;           // (1, 2048, 256)
    (void)in_sizes; (void)n_in; (void)out_size;

    float* normals;
    cudaGetSymbolAddress((void**)&normals, g_normals);

    knn_normals_kernel<<<NPTS / 8, 256>>>(points, normals);
    ppf_kernel<<<NPTS, 256>>>(points, normals, W, b, out);
}

// round 8
// speedup vs baseline: 8.7371x; 1.7893x over previous
#include <cuda_runtime.h>
#include <cuda_bf16.h>
#include <math.h>
#include <float.h>

#define NPTS 2048
#define KNN  10
#define OUTF 256

// _rn intrinsics: immune to compiler fast-math; used on all eigen/kNN-critical math
#define FMUL(a,b)  __fmul_rn((a),(b))
#define FADD(a,b)  __fadd_rn((a),(b))
#define FSUB(a,b)  __fsub_rn((a),(b))
#define FDIV(a,b)  __fdiv_rn((a),(b))
#define FSQRT(a)   __fsqrt_rn((a))

// normals in SoA: [0..N) = x, [N..2N) = y, [2N..3N) = z
__device__ float g_normals[NPTS * 3];

// ---------------------------------------------------------------------------
// LAPACK fp32 building blocks (netlib-faithful, LAPACK >= 3.10 conventions)
// ---------------------------------------------------------------------------

__device__ __forceinline__ float f_sign(float a, float b) {
    return (b >= 0.f) ? fabsf(a) : -fabsf(a);
}

__device__ __forceinline__ float slapy2f(float x, float y) {
    float xa = fabsf(x), ya = fabsf(y);
    float w = fmaxf(xa, ya), z = fminf(xa, ya);
    if (z == 0.f) return w;
    float t = FDIV(z, w);
    return FMUL(w, FSQRT(FADD(1.f, FMUL(t, t))));
}

// LAPACK 3.10+ slartg: c >= 0 always
__device__ __forceinline__ void slartgf(float f, float g, float* c, float* s, float* r) {
    if (g == 0.f)      { *c = 1.f; *s = 0.f; *r = f; }
    else if (f == 0.f) { *c = 0.f; *s = (g >= 0.f) ? 1.f : -1.f; *r = fabsf(g); }
    else {
        float d  = FSQRT(FADD(FMUL(f, f), FMUL(g, g)));
        float rr = (f >= 0.f) ? d : -d;
        *c = FDIV(fabsf(f), d);
        *s = FDIV(g, rr);
        *r = rr;
    }
}

__device__ void slaev2f(float a, float b, float c,
                        float* rt1, float* rt2, float* cs1, float* sn1) {
    float sm  = FADD(a, c);
    float df  = FSUB(a, c);
    float adf = fabsf(df);
    float tb  = FADD(b, b);
    float ab  = fabsf(tb);
    float acmx, acmn;
    if (fabsf(a) > fabsf(c)) { acmx = a; acmn = c; } else { acmx = c; acmn = a; }
    float rt;
    if (adf > ab) {
        float t = FDIV(ab, adf);
        rt = FMUL(adf, FSQRT(FADD(1.f, FMUL(t, t))));
    } else if (adf < ab) {
        float t = FDIV(adf, ab);
        rt = FMUL(ab, FSQRT(FADD(1.f, FMUL(t, t))));
    } else {
        rt = FMUL(ab, FSQRT(2.f));
    }
    int sgn1;
    if (sm < 0.f) {
        *rt1 = FMUL(0.5f, FSUB(sm, rt)); sgn1 = -1;
        *rt2 = FSUB(FMUL(FDIV(acmx, *rt1), acmn), FMUL(FDIV(b, *rt1), b));
    } else if (sm > 0.f) {
        *rt1 = FMUL(0.5f, FADD(sm, rt)); sgn1 = 1;
        *rt2 = FSUB(FMUL(FDIV(acmx, *rt1), acmn), FMUL(FDIV(b, *rt1), b));
    } else {
        *rt1 = FMUL(0.5f, rt); *rt2 = FMUL(-0.5f, rt); sgn1 = 1;
    }
    float cs; int sgn2;
    if (df >= 0.f) { cs = FADD(df, rt); sgn2 =  1; }
    else           { cs = FSUB(df, rt); sgn2 = -1; }
    float acs = fabsf(cs);
    if (acs > ab) {
        float ct = FDIV(-tb, cs);
        *sn1 = FDIV(1.f, FSQRT(FADD(1.f, FMUL(ct, ct))));
        *cs1 = FMUL(ct, *sn1);
    } else {
        if (ab == 0.f) { *cs1 = 1.f; *sn1 = 0.f; }
        else {
            float tn = FDIV(-cs, tb);
            *cs1 = FDIV(1.f, FSQRT(FADD(1.f, FMUL(tn, tn))));
            *sn1 = FMUL(tn, *cs1);
        }
    }
    if (sgn1 == sgn2) { float tn = *cs1; *cs1 = -(*sn1); *sn1 = tn; }
}

__device__ void slasr_b(float* z, int lcol, int mm, const float* wc, const float* ws) {
    for (int j = mm - 1; j >= 1; --j) {
        float c = wc[lcol - 2 + j], s = ws[lcol - 2 + j];
        if (c != 1.f || s != 0.f) {
            int ca = lcol + j - 1;
            int cb = ca - 1;
            #pragma unroll
            for (int r = 0; r < 3; ++r) {
                float temp = z[ca * 3 + r];
                z[ca * 3 + r] = FSUB(FMUL(c, temp), FMUL(s, z[cb * 3 + r]));
                z[cb * 3 + r] = FADD(FMUL(s, temp), FMUL(c, z[cb * 3 + r]));
            }
        }
    }
}
__device__ void slasr_f(float* z, int lcol, int mm, const float* wc, const float* ws) {
    for (int j = 1; j <= mm - 1; ++j) {
        float c = wc[lcol - 2 + j], s = ws[lcol - 2 + j];
        if (c != 1.f || s != 0.f) {
            int ca = lcol + j - 1;
            int cb = ca - 1;
            #pragma unroll
            for (int r = 0; r < 3; ++r) {
                float temp = z[ca * 3 + r];
                z[ca * 3 + r] = FSUB(FMUL(c, temp), FMUL(s, z[cb * 3 + r]));
                z[cb * 3 + r] = FADD(FMUL(s, temp), FMUL(c, z[cb * 3 + r]));
            }
        }
    }
}

// ssteqr('I', n=3) — faithful control-flow translation of netlib ssteqr
__device__ void ssteqr3(float* d, float* e, float* z) {
    const float eps    = 5.9604645e-8f;
    const float eps2   = eps * eps;
    const float safmin = 1.17549435e-38f;
    float wc[2], ws[2];
    int l1, l, lsv, lend, lendsv, m, i, jtot, nmaxit;
    float p, g, r, s, c, f, bb, rt1, rt2, anorm, tst;
    nmaxit = 90; jtot = 0; l1 = 1;

L10:
    if (l1 > 3) goto L160;
    if (l1 > 1) e[l1 - 2] = 0.f;
    if (l1 <= 2) {
        for (m = l1; m <= 2; ++m) {
            tst = fabsf(e[m - 1]);
            if (tst == 0.f) goto L30;
            if (tst <= FMUL(FMUL(FSQRT(fabsf(d[m - 1])), FSQRT(fabsf(d[m]))), eps)) {
                e[m - 1] = 0.f; goto L30;
            }
        }
    }
    m = 3;
L30:
    l = l1; lsv = l; lend = m; lendsv = lend; l1 = m + 1;
    if (lend == l) goto L10;
    anorm = 0.f;
    for (i = l; i <= lend; ++i)     anorm = fmaxf(anorm, fabsf(d[i - 1]));
    for (i = l; i <= lend - 1; ++i) anorm = fmaxf(anorm, fabsf(e[i - 1]));
    if (anorm == 0.f) goto L10;
    if (fabsf(d[lend - 1]) < fabsf(d[l - 1])) { lend = lsv; l = lendsv; }
    if (lend > l) goto L40; else goto L90;

L40: // QL
    if (l != lend) {
        for (m = l; m <= lend - 1; ++m) {
            tst = FMUL(e[m - 1], e[m - 1]);
            if (tst <= FADD(FMUL(FMUL(eps2, fabsf(d[m - 1])), fabsf(d[m])), safmin)) goto L60;
        }
    }
    m = lend;
L60:
    if (m < lend) e[m - 1] = 0.f;
    p = d[l - 1];
    if (m == l) goto L80;
    if (m == l + 1) {
        slaev2f(d[l - 1], e[l - 1], d[l], &rt1, &rt2, &c, &s);
        wc[l - 1] = c; ws[l - 1] = s;
        slasr_b(z, l, 2, wc, ws);
        d[l - 1] = rt1; d[l] = rt2; e[l - 1] = 0.f;
        l += 2;
        if (l <= lend) goto L40;
        goto L140;
    }
    if (jtot == nmaxit) goto L140;
    jtot++;
    g = FDIV(FSUB(d[l], p), FMUL(2.f, e[l - 1]));
    r = slapy2f(g, 1.f);
    g = FADD(FSUB(d[m - 1], p), FDIV(e[l - 1], FADD(g, f_sign(r, g))));
    s = 1.f; c = 1.f; p = 0.f;
    for (i = m - 1; i >= l; --i) {
        f  = FMUL(s, e[i - 1]);
        bb = FMUL(c, e[i - 1]);
        slartgf(g, f, &c, &s, &r);
        if (i != m - 1) e[i] = r;
        g = FSUB(d[i], p);
        r = FADD(FMUL(FSUB(d[i - 1], g), s), FMUL(FMUL(2.f, c), bb));
        p = FMUL(s, r);
        d[i] = FADD(g, p);
        g = FSUB(FMUL(c, r), bb);
        wc[i - 1] = c; ws[i - 1] = -s;
    }
    slasr_b(z, l, m - l + 1, wc, ws);
    d[l - 1] = FSUB(d[l - 1], p);
    e[l - 1] = g;
    goto L40;
L80:
    d[l - 1] = p;
    l++;
    if (l <= lend) goto L40;
    goto L140;

L90: // QR
    if (l != lend) {
        for (m = l; m >= lend + 1; --m) {
            tst = FMUL(e[m - 2], e[m - 2]);
            if (tst <= FADD(FMUL(FMUL(eps2, fabsf(d[m - 1])), fabsf(d[m - 2])), safmin)) goto L110;
        }
    }
    m = lend;
L110:
    if (m > lend) e[m - 2] = 0.f;
    p = d[l - 1];
    if (m == l) goto L130;
    if (m == l - 1) {
        slaev2f(d[l - 2], e[l - 2], d[l - 1], &rt1, &rt2, &c, &s);
        wc[m - 1] = c; ws[m - 1] = s;
        slasr_f(z, l - 1, 2, wc, ws);
        d[l - 2] = rt1; d[l - 1] = rt2; e[l - 2] = 0.f;
        l -= 2;
        if (l >= lend) goto L90;
        goto L140;
    }
    if (jtot == nmaxit) goto L140;
    jtot++;
    g = FDIV(FSUB(d[l - 2], p), FMUL(2.f, e[l - 2]));
    r = slapy2f(g, 1.f);
    g = FADD(FSUB(d[m - 1], p), FDIV(e[l - 2], FADD(g, f_sign(r, g))));
    s = 1.f; c = 1.f; p = 0.f;
    for (i = m; i <= l - 1; ++i) {
        f  = FMUL(s, e[i - 1]);
        bb = FMUL(c, e[i - 1]);
        slartgf(g, f, &c, &s, &r);
        if (i != m) e[i - 2] = r;
        g = FSUB(d[i - 1], p);
        r = FADD(FMUL(FSUB(d[i], g), s), FMUL(FMUL(2.f, c), bb));
        p = FMUL(s, r);
        d[i - 1] = FADD(g, p);
        g = FSUB(FMUL(c, r), bb);
        wc[i - 1] = c; ws[i - 1] = s;
    }
    slasr_f(z, m, l - m + 1, wc, ws);
    d[l - 1] = FSUB(d[l - 1], p);
    e[l - 2] = g;
    goto L90;
L130:
    d[l - 1] = p;
    l--;
    if (l >= lend) goto L90;
    goto L140;

L140:
    if (jtot < nmaxit) goto L10;
    goto L160;

L160:
    for (int ii = 2; ii <= 3; ++ii) {
        int ia = ii - 1, k = ia;
        float pp = d[ia - 1];
        for (int j = ii; j <= 3; ++j)
            if (d[j - 1] < pp) { k = j; pp = d[j - 1]; }
        if (k != ia) {
            d[k - 1] = d[ia - 1]; d[ia - 1] = pp;
            #pragma unroll
            for (int rr2 = 0; rr2 < 3; ++rr2) {
                float t = z[(ia - 1) * 3 + rr2];
                z[(ia - 1) * 3 + rr2] = z[(k - 1) * 3 + rr2];
                z[(k - 1) * 3 + rr2] = t;
            }
        }
    }
}

__device__ void smallest_eigvec3(float a11, float a21, float a31,
                                 float a22, float a32, float a33,
                                 float* nrm) {
    float alpha = a21;
    float xnorm = fabsf(a31);
    float tau1, v3, e1;
    if (xnorm == 0.f) {
        tau1 = 0.f; e1 = alpha; v3 = 0.f;
    } else {
        float beta = -f_sign(slapy2f(alpha, xnorm), alpha);
        tau1 = FDIV(FSUB(beta, alpha), beta);
        v3   = FMUL(a31, FDIV(1.f, FSUB(alpha, beta)));
        e1   = beta;
    }
    if (tau1 != 0.f) {
        float x1 = FMUL(tau1, FADD(a22, FMUL(a32, v3)));
        float x2 = FMUL(tau1, FADD(a32, FMUL(a33, v3)));
        float al = FMUL(FMUL(-0.5f, tau1), FADD(x1, FMUL(x2, v3)));
        float w1 = FADD(x1, al);
        float w2 = FADD(x2, FMUL(al, v3));
        a22 = FSUB(a22, FMUL(2.f, w1));
        a32 = FSUB(a32, FADD(FMUL(v3, w1), w2));
        a33 = FSUB(a33, FMUL(2.f, FMUL(v3, w2)));
    }
    float d[3] = {a11, a22, a33};
    float e[2] = {e1, a32};
    float z[9] = {1.f, 0.f, 0.f, 0.f, 1.f, 0.f, 0.f, 0.f, 1.f};

    ssteqr3(d, e, z);

    float z0 = z[0], z1 = z[1], z2 = z[2];
    if (tau1 != 0.f) {
        float t = FMUL(tau1, FADD(z1, FMUL(v3, z2)));
        z1 = FSUB(z1, t);
        z2 = FSUB(z2, FMUL(t, v3));
    }
    nrm[0] = z0; nrm[1] = z1; nrm[2] = z2;
}

// ---------------------------------------------------------------------------
// Kernel 1: warp-per-point kNN (fully register-resident top-11) + covariance
// + smallest eigenvector. Packed (float-bits(sq) << 32 | idx) keys make u64
// order == (sq, idx) lexicographic == top_k's stable tie order.
// ---------------------------------------------------------------------------
__global__ void __launch_bounds__(256)
knn_normals_kernel(const float* __restrict__ pts, float* __restrict__ normals) {
    __shared__ float sx[NPTS], sy[NPTS], sz[NPTS];
    int tid = threadIdx.x;
    for (int j = tid; j < NPTS; j += 256) {
        sx[j] = pts[j * 3 + 0];
        sy[j] = pts[j * 3 + 1];
        sz[j] = pts[j * 3 + 2];
    }
    __syncthreads();

    int warp = tid >> 5, lane = tid & 31;
    int i = blockIdx.x * 8 + warp;

    float pix = sx[i], piy = sy[i], piz = sz[i];

    // per-lane sorted top-11, registers only (static indexing throughout)
    unsigned long long kv[KNN + 1];
    #pragma unroll
    for (int q = 0; q <= KNN; ++q) kv[q] = 0xFFFFFFFFFFFFFFFFull;

    #pragma unroll 4
    for (int j = lane; j < NPTS; j += 32) {
        float dx = FSUB(pix, sx[j]);
        float dy = FSUB(piy, sy[j]);
        float dz = FSUB(piz, sz[j]);
        float sq = FADD(FADD(FMUL(dx, dx), FMUL(dy, dy)), FMUL(dz, dz));
        unsigned long long key =
            ((unsigned long long)__float_as_uint(sq) << 32) | (unsigned)j;
        if (key < kv[KNN]) {
            kv[KNN] = key;
            // single bubble pass: carries the new key up to its sorted slot
            #pragma unroll
            for (int q = KNN; q > 0; --q) {
                unsigned long long a = kv[q - 1], b = kv[q];
                kv[q - 1] = (a < b) ? a : b;
                kv[q]     = (a < b) ? b : a;
            }
        }
    }

    // 11-round warp merge; each lane's head stays at kv[0] (shift-down on consume)
    int nbr[KNN + 1];
    #pragma unroll
    for (int r = 0; r <= KNN; ++r) {
        unsigned long long mykey = kv[0];
        unsigned long long m = mykey;
        #pragma unroll
        for (int off = 16; off > 0; off >>= 1) {
            unsigned long long o = __shfl_xor_sync(0xFFFFFFFFu, m, off);
            m = (o < m) ? o : m;
        }
        nbr[r] = (int)(unsigned)(m & 0xFFFFFFFFull);
        if (mykey == m) {              // unique owner (idx embedded in key)
            #pragma unroll
            for (int q = 0; q < KNN; ++q) kv[q] = kv[q + 1];
            kv[KNN] = 0xFFFFFFFFFFFFFFFFull;
        }
    }

    if (lane == 0) {
        // neighbors = nbr[1..10] (slot 0 is self, as reference's knn[:,1:])
        float nx[KNN], ny[KNN], nz[KNN];
        float mx = 0.f, my = 0.f, mz = 0.f;
        #pragma unroll
        for (int k = 0; k < KNN; ++k) {
            int j = nbr[k + 1];
            nx[k] = sx[j]; ny[k] = sy[j]; nz[k] = sz[j];
            mx = FADD(mx, nx[k]); my = FADD(my, ny[k]); mz = FADD(mz, nz[k]);
        }
        mx = FDIV(mx, 10.f); my = FDIV(my, 10.f); mz = FDIV(mz, 10.f);

        float c00 = 0.f, c10 = 0.f, c20 = 0.f, c11 = 0.f, c21 = 0.f, c22 = 0.f;
        #pragma unroll
        for (int k = 0; k < KNN; ++k) {
            float cx = FSUB(nx[k], mx);
            float cy = FSUB(ny[k], my);
            float cz = FSUB(nz[k], mz);
            c00 = FADD(c00, FMUL(cx, cx));
            c10 = FADD(c10, FMUL(cy, cx));
            c20 = FADD(c20, FMUL(cz, cx));
            c11 = FADD(c11, FMUL(cy, cy));
            c21 = FADD(c21, FMUL(cz, cy));
            c22 = FADD(c22, FMUL(cz, cz));
        }
        c00 = FDIV(c00, 10.f); c10 = FDIV(c10, 10.f); c20 = FDIV(c20, 10.f);
        c11 = FDIV(c11, 10.f); c21 = FDIV(c21, 10.f); c22 = FDIV(c22, 10.f);

        float nrm[3];
        smallest_eigvec3(c00, c10, c20, c11, c21, c22, nrm);
        normals[i]            = nrm[0];   // SoA: x
        normals[NPTS + i]     = nrm[1];   // y
        normals[2 * NPTS + i] = nrm[2];   // z
    }
}

// ---------------------------------------------------------------------------
// Fast atan2 for y >= 0 (result in [0, pi]); cephes coefficients, ~1e-7 abs err
// ---------------------------------------------------------------------------
__device__ __forceinline__ float fast_atan2_pos(float y, float x) {
    const float PI    = 3.14159265358979323846f;
    const float PIO2  = 1.57079632679489661923f;
    const float PIO4  = 0.78539816339744830962f;
    const float TAN8  = 0.41421356237309504880f;

    float ax = fabsf(x);
    float mn = fminf(y, ax), mx = fmaxf(y, ax);
    float t = (mx == 0.f) ? 0.f : __fdividef(mn, mx);

    float add = 0.f;
    if (t > TAN8) { t = __fdividef(t - 1.f, t + 1.f); add = PIO4; }

    float z = t * t;
    float p = 8.05374449538e-2f;
    p = p * z - 1.38776856032e-1f;
    p = p * z + 1.99777106478e-1f;
    p = p * z - 3.33329491539e-1f;
    float r = fmaf(p * z, t, t) + add;

    if (y > ax)  r = PIO2 - r;
    if (x < 0.f) r = PI - r;
    return r;
}

// ---------------------------------------------------------------------------
// Kernel 2: PPF mean over j (block per point i) + 4->256 linear layer.
// Points in smem (25KB -> ~9 blocks/SM); normals coalesced __ldg from SoA.
// ---------------------------------------------------------------------------
__global__ void __launch_bounds__(256)
ppf_kernel(const float* __restrict__ pts, const float* __restrict__ normals,
           const float* __restrict__ W, const float* __restrict__ b,
           float* __restrict__ out) {
    __shared__ float sx[NPTS], sy[NPTS], sz[NPTS];
    __shared__ float red[32];
    int tid = threadIdx.x;
    for (int j = tid; j < NPTS; j += 256) {
        sx[j] = pts[j * 3 + 0];
        sy[j] = pts[j * 3 + 1];
        sz[j] = pts[j * 3 + 2];
    }
    __syncthreads();

    const float* gnx = normals;
    const float* gny = normals + NPTS;
    const float* gnz = normals + 2 * NPTS;

    int i = blockIdx.x;
    float pix = sx[i], piy = sy[i], piz = sz[i];
    float nix = __ldg(&gnx[i]), niy = __ldg(&gny[i]), niz = __ldg(&gnz[i]);

    float s0 = 0.f, s1 = 0.f, s2 = 0.f, s3 = 0.f;
    #pragma unroll
    for (int jj = 0; jj < NPTS / 256; ++jj) {
        int j = tid + jj * 256;
        float dx = pix - sx[j], dy = piy - sy[j], dz = piz - sz[j];
        float njx = __ldg(&gnx[j]), njy = __ldg(&gny[j]), njz = __ldg(&gnz[j]);

        float sq = dx * dx + dy * dy + dz * dz;
        float dn = (sq > 0.f) ? sq * rsqrtf(sq) : 0.f;

        // angle(ni, d)
        float cx = niy * dz - niz * dy;
        float cy = niz * dx - nix * dz;
        float cz = nix * dy - niy * dx;
        float csq = cx * cx + cy * cy + cz * cz;
        float cn  = (csq > 0.f) ? csq * rsqrtf(csq) : 0.f;
        float dot = nix * dx + niy * dy + niz * dz;
        float a1 = fast_atan2_pos(cn, dot);

        // angle(nj, d)
        cx = njy * dz - njz * dy;
        cy = njz * dx - njx * dz;
        cz = njx * dy - njy * dx;
        csq = cx * cx + cy * cy + cz * cz;
        cn  = (csq > 0.f) ? csq * rsqrtf(csq) : 0.f;
        dot = njx * dx + njy * dy + njz * dz;
        float a2 = fast_atan2_pos(cn, dot);

        // angle(ni, nj)
        cx = niy * njz - niz * njy;
        cy = niz * njx - nix * njz;
        cz = nix * njy - niy * njx;
        csq = cx * cx + cy * cy + cz * cz;
        cn  = (csq > 0.f) ? csq * rsqrtf(csq) : 0.f;
        dot = nix * njx + niy * njy + niz * njz;
        float a3 = fast_atan2_pos(cn, dot);

        s0 += dn; s1 += a1; s2 += a2; s3 += a3;
    }

    #pragma unroll
    for (int off = 16; off > 0; off >>= 1) {
        s0 += __shfl_down_sync(0xFFFFFFFFu, s0, off);
        s1 += __shfl_down_sync(0xFFFFFFFFu, s1, off);
        s2 += __shfl_down_sync(0xFFFFFFFFu, s2, off);
        s3 += __shfl_down_sync(0xFFFFFFFFu, s3, off);
    }
    int w = tid >> 5, lane = tid & 31;
    if (lane == 0) {
        red[w * 4 + 0] = s0; red[w * 4 + 1] = s1;
        red[w * 4 + 2] = s2; red[w * 4 + 3] = s3;
    }
    __syncthreads();
    if (tid == 0) {
        float t0 = 0.f, t1 = 0.f, t2 = 0.f, t3 = 0.f;
        #pragma unroll
        for (int q = 0; q < 8; ++q) {
            t0 += red[q * 4 + 0]; t1 += red[q * 4 + 1];
            t2 += red[q * 4 + 2]; t3 += red[q * 4 + 3];
        }
        red[0] = t0 / 2048.f; red[1] = t1 / 2048.f;
        red[2] = t2 / 2048.f; red[3] = t3 / 2048.f;
    }
    __syncthreads();
    float f0 = red[0], f1 = red[1], f2 = red[2], f3 = red[3];

    float acc = f0 * W[tid * 4 + 0];
    acc = acc + f1 * W[tid * 4 + 1];
    acc = acc + f2 * W[tid * 4 + 2];
    acc = acc + f3 * W[tid * 4 + 3];
    acc = acc + b[tid];
    out[i * OUTF + tid] = acc;
}

extern "C" void kernel_launch(void* const* d_in, const int* in_sizes, int n_in,
                              void* d_out, int out_size) {
    const float* points = (const float*)d_in[0];   // (1, 2048, 3)
    const float* W      = (const float*)d_in[1];   // (256, 4)
    const float* b      = (const float*)d_in[2];   // (256,)
    float* out          = (float*)d_out;           // (1, 2048, 256)
    (void)in_sizes; (void)n_in; (void)out_size;

    float* normals;
    cudaGetSymbolAddress((void**)&normals, g_normals);

    knn_normals_kernel<<<NPTS / 8, 256>>>(points, normals);
    ppf_kernel<<<NPTS, 256>>>(points, normals, W, b, out);
}

// round 9
// speedup vs baseline: 8.9293x; 1.0220x over previous
#include <cuda_runtime.h>
#include <cuda_bf16.h>
#include <math.h>
#include <float.h>

#define NPTS 2048
#define KNN  10
#define OUTF 256

// _rn intrinsics: immune to compiler fast-math; used on all eigen/kNN-critical math
#define FMUL(a,b)  __fmul_rn((a),(b))
#define FADD(a,b)  __fadd_rn((a),(b))
#define FSUB(a,b)  __fsub_rn((a),(b))
#define FDIV(a,b)  __fdiv_rn((a),(b))
#define FSQRT(a)   __fsqrt_rn((a))

// normals SoA: [0..N)=x, [N..2N)=y, [2N..3N)=z, [3N..4N)=|n|^2
__device__ float g_normals[NPTS * 4];

// ---------------------------------------------------------------------------
// LAPACK fp32 building blocks (netlib-faithful, LAPACK >= 3.10 conventions)
// ---------------------------------------------------------------------------

__device__ __forceinline__ float f_sign(float a, float b) {
    return (b >= 0.f) ? fabsf(a) : -fabsf(a);
}

__device__ __forceinline__ float slapy2f(float x, float y) {
    float xa = fabsf(x), ya = fabsf(y);
    float w = fmaxf(xa, ya), z = fminf(xa, ya);
    if (z == 0.f) return w;
    float t = FDIV(z, w);
    return FMUL(w, FSQRT(FADD(1.f, FMUL(t, t))));
}

// LAPACK 3.10+ slartg: c >= 0 always
__device__ __forceinline__ void slartgf(float f, float g, float* c, float* s, float* r) {
    if (g == 0.f)      { *c = 1.f; *s = 0.f; *r = f; }
    else if (f == 0.f) { *c = 0.f; *s = (g >= 0.f) ? 1.f : -1.f; *r = fabsf(g); }
    else {
        float d  = FSQRT(FADD(FMUL(f, f), FMUL(g, g)));
        float rr = (f >= 0.f) ? d : -d;
        *c = FDIV(fabsf(f), d);
        *s = FDIV(g, rr);
        *r = rr;
    }
}

__device__ void slaev2f(float a, float b, float c,
                        float* rt1, float* rt2, float* cs1, float* sn1) {
    float sm  = FADD(a, c);
    float df  = FSUB(a, c);
    float adf = fabsf(df);
    float tb  = FADD(b, b);
    float ab  = fabsf(tb);
    float acmx, acmn;
    if (fabsf(a) > fabsf(c)) { acmx = a; acmn = c; } else { acmx = c; acmn = a; }
    float rt;
    if (adf > ab) {
        float t = FDIV(ab, adf);
        rt = FMUL(adf, FSQRT(FADD(1.f, FMUL(t, t))));
    } else if (adf < ab) {
        float t = FDIV(adf, ab);
        rt = FMUL(ab, FSQRT(FADD(1.f, FMUL(t, t))));
    } else {
        rt = FMUL(ab, FSQRT(2.f));
    }
    int sgn1;
    if (sm < 0.f) {
        *rt1 = FMUL(0.5f, FSUB(sm, rt)); sgn1 = -1;
        *rt2 = FSUB(FMUL(FDIV(acmx, *rt1), acmn), FMUL(FDIV(b, *rt1), b));
    } else if (sm > 0.f) {
        *rt1 = FMUL(0.5f, FADD(sm, rt)); sgn1 = 1;
        *rt2 = FSUB(FMUL(FDIV(acmx, *rt1), acmn), FMUL(FDIV(b, *rt1), b));
    } else {
        *rt1 = FMUL(0.5f, rt); *rt2 = FMUL(-0.5f, rt); sgn1 = 1;
    }
    float cs; int sgn2;
    if (df >= 0.f) { cs = FADD(df, rt); sgn2 =  1; }
    else           { cs = FSUB(df, rt); sgn2 = -1; }
    float acs = fabsf(cs);
    if (acs > ab) {
        float ct = FDIV(-tb, cs);
        *sn1 = FDIV(1.f, FSQRT(FADD(1.f, FMUL(ct, ct))));
        *cs1 = FMUL(ct, *sn1);
    } else {
        if (ab == 0.f) { *cs1 = 1.f; *sn1 = 0.f; }
        else {
            float tn = FDIV(-cs, tb);
            *cs1 = FDIV(1.f, FSQRT(FADD(1.f, FMUL(tn, tn))));
            *sn1 = FMUL(tn, *cs1);
        }
    }
    if (sgn1 == sgn2) { float tn = *cs1; *cs1 = -(*sn1); *sn1 = tn; }
}

// ---------------------------------------------------------------------------
// ssteqr('I', n=3), fully register-resident: all state is named scalars,
// dynamic indices resolved through select-based accessors (no local memory).
// Control flow and arithmetic identical to the netlib array version.
// ---------------------------------------------------------------------------
__device__ void ssteqr3_reg(float& d0, float& d1, float& d2,
                            float& e0, float& e1,
                            float& za0, float& za1, float& za2,
                            float& zb0, float& zb1, float& zb2,
                            float& zc0, float& zc1, float& zc2) {
    const float eps    = 5.9604645e-8f;
    const float eps2   = eps * eps;
    const float safmin = 1.17549435e-38f;
    float wc0 = 0.f, wc1 = 0.f, ws0 = 0.f, ws1 = 0.f;

    auto dget = [&](int i) -> float { return i == 0 ? d0 : (i == 1 ? d1 : d2); };
    auto dset = [&](int i, float v) { if (i == 0) d0 = v; else if (i == 1) d1 = v; else d2 = v; };
    auto eget = [&](int i) -> float { return i == 0 ? e0 : e1; };
    auto eset = [&](int i, float v) { if (i == 0) e0 = v; else e1 = v; };
    auto wcget = [&](int i) -> float { return i == 0 ? wc0 : wc1; };
    auto wcset = [&](int i, float v) { if (i == 0) wc0 = v; else wc1 = v; };
    auto wsget = [&](int i) -> float { return i == 0 ? ws0 : ws1; };
    auto wsset = [&](int i, float v) { if (i == 0) ws0 = v; else ws1 = v; };

    // rotate column pair (cb1, cb1+1), cb1 is the 1-based lower column in {1,2}
    auto rot = [&](int cb1, float c, float s) {
        if (cb1 == 1) {
            float t;
            t = zb0; zb0 = FSUB(FMUL(c, t), FMUL(s, za0)); za0 = FADD(FMUL(s, t), FMUL(c, za0));
            t = zb1; zb1 = FSUB(FMUL(c, t), FMUL(s, za1)); za1 = FADD(FMUL(s, t), FMUL(c, za1));
            t = zb2; zb2 = FSUB(FMUL(c, t), FMUL(s, za2)); za2 = FADD(FMUL(s, t), FMUL(c, za2));
        } else {
            float t;
            t = zc0; zc0 = FSUB(FMUL(c, t), FMUL(s, zb0)); zb0 = FADD(FMUL(s, t), FMUL(c, zb0));
            t = zc1; zc1 = FSUB(FMUL(c, t), FMUL(s, zb1)); zb1 = FADD(FMUL(s, t), FMUL(c, zb1));
            t = zc2; zc2 = FSUB(FMUL(c, t), FMUL(s, zb2)); zb2 = FADD(FMUL(s, t), FMUL(c, zb2));
        }
    };
    auto slasr_bL = [&](int lcol, int mm) {   // 'B': j = mm-1 .. 1
        for (int j = mm - 1; j >= 1; --j) {
            float c = wcget(lcol - 2 + j), s = wsget(lcol - 2 + j);
            if (c != 1.f || s != 0.f) rot(lcol + j - 1, c, s);
        }
    };
    auto slasr_fL = [&](int lcol, int mm) {   // 'F': j = 1 .. mm-1
        for (int j = 1; j <= mm - 1; ++j) {
            float c = wcget(lcol - 2 + j), s = wsget(lcol - 2 + j);
            if (c != 1.f || s != 0.f) rot(lcol + j - 1, c, s);
        }
    };

    int l1, l, lsv, lend, lendsv, m, i, jtot, nmaxit;
    float p, g, r, s, c, f, bb, rt1, rt2, anorm, tst;
    nmaxit = 90; jtot = 0; l1 = 1;

L10:
    if (l1 > 3) goto L160;
    if (l1 > 1) eset(l1 - 2, 0.f);
    if (l1 <= 2) {
        for (m = l1; m <= 2; ++m) {
            tst = fabsf(eget(m - 1));
            if (tst == 0.f) goto L30;
            if (tst <= FMUL(FMUL(FSQRT(fabsf(dget(m - 1))), FSQRT(fabsf(dget(m)))), eps)) {
                eset(m - 1, 0.f); goto L30;
            }
        }
    }
    m = 3;
L30:
    l = l1; lsv = l; lend = m; lendsv = lend; l1 = m + 1;
    if (lend == l) goto L10;
    anorm = 0.f;
    for (i = l; i <= lend; ++i)     anorm = fmaxf(anorm, fabsf(dget(i - 1)));
    for (i = l; i <= lend - 1; ++i) anorm = fmaxf(anorm, fabsf(eget(i - 1)));
    if (anorm == 0.f) goto L10;
    if (fabsf(dget(lend - 1)) < fabsf(dget(l - 1))) { lend = lsv; l = lendsv; }
    if (lend > l) goto L40; else goto L90;

L40: // QL
    if (l != lend) {
        for (m = l; m <= lend - 1; ++m) {
            tst = FMUL(eget(m - 1), eget(m - 1));
            if (tst <= FADD(FMUL(FMUL(eps2, fabsf(dget(m - 1))), fabsf(dget(m))), safmin)) goto L60;
        }
    }
    m = lend;
L60:
    if (m < lend) eset(m - 1, 0.f);
    p = dget(l - 1);
    if (m == l) goto L80;
    if (m == l + 1) {
        slaev2f(dget(l - 1), eget(l - 1), dget(l), &rt1, &rt2, &c, &s);
        wcset(l - 1, c); wsset(l - 1, s);
        slasr_bL(l, 2);
        dset(l - 1, rt1); dset(l, rt2); eset(l - 1, 0.f);
        l += 2;
        if (l <= lend) goto L40;
        goto L140;
    }
    if (jtot == nmaxit) goto L140;
    jtot++;
    g = FDIV(FSUB(dget(l), p), FMUL(2.f, eget(l - 1)));
    r = slapy2f(g, 1.f);
    g = FADD(FSUB(dget(m - 1), p), FDIV(eget(l - 1), FADD(g, f_sign(r, g))));
    s = 1.f; c = 1.f; p = 0.f;
    for (i = m - 1; i >= l; --i) {
        f  = FMUL(s, eget(i - 1));
        bb = FMUL(c, eget(i - 1));
        slartgf(g, f, &c, &s, &r);
        if (i != m - 1) eset(i, r);
        g = FSUB(dget(i), p);
        r = FADD(FMUL(FSUB(dget(i - 1), g), s), FMUL(FMUL(2.f, c), bb));
        p = FMUL(s, r);
        dset(i, FADD(g, p));
        g = FSUB(FMUL(c, r), bb);
        wcset(i - 1, c); wsset(i - 1, -s);
    }
    slasr_bL(l, m - l + 1);
    dset(l - 1, FSUB(dget(l - 1), p));
    eset(l - 1, g);
    goto L40;
L80:
    dset(l - 1, p);
    l++;
    if (l <= lend) goto L40;
    goto L140;

L90: // QR
    if (l != lend) {
        for (m = l; m >= lend + 1; --m) {
            tst = FMUL(eget(m - 2), eget(m - 2));
            if (tst <= FADD(FMUL(FMUL(eps2, fabsf(dget(m - 1))), fabsf(dget(m - 2))), safmin)) goto L110;
        }
    }
    m = lend;
L110:
    if (m > lend) eset(m - 2, 0.f);
    p = dget(l - 1);
    if (m == l) goto L130;
    if (m == l - 1) {
        slaev2f(dget(l - 2), eget(l - 2), dget(l - 1), &rt1, &rt2, &c, &s);
        wcset(m - 1, c); wsset(m - 1, s);
        slasr_fL(l - 1, 2);
        dset(l - 2, rt1); dset(l - 1, rt2); eset(l - 2, 0.f);
        l -= 2;
        if (l >= lend) goto L90;
        goto L140;
    }
    if (jtot == nmaxit) goto L140;
    jtot++;
    g = FDIV(FSUB(dget(l - 2), p), FMUL(2.f, eget(l - 2)));
    r = slapy2f(g, 1.f);
    g = FADD(FSUB(dget(m - 1), p), FDIV(eget(l - 2), FADD(g, f_sign(r, g))));
    s = 1.f; c = 1.f; p = 0.f;
    for (i = m; i <= l - 1; ++i) {
        f  = FMUL(s, eget(i - 1));
        bb = FMUL(c, eget(i - 1));
        slartgf(g, f, &c, &s, &r);
        if (i != m) eset(i - 2, r);
        g = FSUB(dget(i - 1), p);
        r = FADD(FMUL(FSUB(dget(i), g), s), FMUL(FMUL(2.f, c), bb));
        p = FMUL(s, r);
        dset(i - 1, FADD(g, p));
        g = FSUB(FMUL(c, r), bb);
        wcset(i - 1, c); wsset(i - 1, s);
    }
    slasr_fL(m, l - m + 1);
    dset(l - 1, FSUB(dget(l - 1), p));
    eset(l - 2, g);
    goto L90;
L130:
    dset(l - 1, p);
    l--;
    if (l >= lend) goto L90;
    goto L140;

L140:
    if (jtot < nmaxit) goto L10;
    goto L160;

L160:
    // selection sort ascending, swapping eigenvector columns
    {
        auto swapcol = [&](int c1, int c2) {   // 0-based, c1 < c2
            float t;
            if (c1 == 0 && c2 == 1) {
                t = za0; za0 = zb0; zb0 = t;
                t = za1; za1 = zb1; zb1 = t;
                t = za2; za2 = zb2; zb2 = t;
            } else if (c1 == 0) {
                t = za0; za0 = zc0; zc0 = t;
                t = za1; za1 = zc1; zc1 = t;
                t = za2; za2 = zc2; zc2 = t;
            } else {
                t = zb0; zb0 = zc0; zc0 = t;
                t = zb1; zb1 = zc1; zc1 = t;
                t = zb2; zb2 = zc2; zc2 = t;
            }
        };
        for (int ii = 2; ii <= 3; ++ii) {
            int ia = ii - 1, k = ia;
            float pp = dget(ia - 1);
            for (int j = ii; j <= 3; ++j)
                if (dget(j - 1) < pp) { k = j; pp = dget(j - 1); }
            if (k != ia) {
                dset(k - 1, dget(ia - 1)); dset(ia - 1, pp);
                swapcol(ia - 1, k - 1);
            }
        }
    }
}

__device__ void smallest_eigvec3(float a11, float a21, float a31,
                                 float a22, float a32, float a33,
                                 float* nrm) {
    // --- ssytd2, n=3, uplo='L': one reflector on A(2:3,1) ---
    float alpha = a21;
    float xnorm = fabsf(a31);
    float tau1, v3, eh;
    if (xnorm == 0.f) {
        tau1 = 0.f; eh = alpha; v3 = 0.f;
    } else {
        float beta = -f_sign(slapy2f(alpha, xnorm), alpha);
        tau1 = FDIV(FSUB(beta, alpha), beta);
        v3   = FMUL(a31, FDIV(1.f, FSUB(alpha, beta)));
        eh   = beta;
    }
    if (tau1 != 0.f) {
        float x1 = FMUL(tau1, FADD(a22, FMUL(a32, v3)));
        float x2 = FMUL(tau1, FADD(a32, FMUL(a33, v3)));
        float al = FMUL(FMUL(-0.5f, tau1), FADD(x1, FMUL(x2, v3)));
        float w1 = FADD(x1, al);
        float w2 = FADD(x2, FMUL(al, v3));
        a22 = FSUB(a22, FMUL(2.f, w1));
        a32 = FSUB(a32, FADD(FMUL(v3, w1), w2));
        a33 = FSUB(a33, FMUL(2.f, FMUL(v3, w2)));
    }
    float d0 = a11, d1 = a22, d2 = a33;
    float e0 = eh, e1 = a32;
    float za0 = 1.f, za1 = 0.f, za2 = 0.f;
    float zb0 = 0.f, zb1 = 1.f, zb2 = 0.f;
    float zc0 = 0.f, zc1 = 0.f, zc2 = 1.f;

    ssteqr3_reg(d0, d1, d2, e0, e1,
                za0, za1, za2, zb0, zb1, zb2, zc0, zc1, zc2);

    // sormtr('L','L','N'): apply H(1) to rows 2:3 of eigvec column 0
    float z0 = za0, z1 = za1, z2 = za2;
    if (tau1 != 0.f) {
        float t = FMUL(tau1, FADD(z1, FMUL(v3, z2)));
        z1 = FSUB(z1, t);
        z2 = FSUB(z2, FMUL(t, v3));
    }
    nrm[0] = z0; nrm[1] = z1; nrm[2] = z2;
}

// ---------------------------------------------------------------------------
// Kernel 1: warp-per-point kNN (register top-11, packed u64 keys == top_k's
// stable (sq, idx) order) + covariance + smallest eigenvector (lane 0).
// ---------------------------------------------------------------------------
__global__ void __launch_bounds__(256)
knn_normals_kernel(const float* __restrict__ pts, float* __restrict__ normals) {
    __shared__ float sx[NPTS], sy[NPTS], sz[NPTS];
    int tid = threadIdx.x;
    for (int j = tid; j < NPTS; j += 256) {
        sx[j] = pts[j * 3 + 0];
        sy[j] = pts[j * 3 + 1];
        sz[j] = pts[j * 3 + 2];
    }
    __syncthreads();

    int warp = tid >> 5, lane = tid & 31;
    int i = blockIdx.x * 8 + warp;

    float pix = sx[i], piy = sy[i], piz = sz[i];

    unsigned long long kv[KNN + 1];
    #pragma unroll
    for (int q = 0; q <= KNN; ++q) kv[q] = 0xFFFFFFFFFFFFFFFFull;

    #pragma unroll 4
    for (int j = lane; j < NPTS; j += 32) {
        float dx = FSUB(pix, sx[j]);
        float dy = FSUB(piy, sy[j]);
        float dz = FSUB(piz, sz[j]);
        float sq = FADD(FADD(FMUL(dx, dx), FMUL(dy, dy)), FMUL(dz, dz));
        unsigned long long key =
            ((unsigned long long)__float_as_uint(sq) << 32) | (unsigned)j;
        if (key < kv[KNN]) {
            kv[KNN] = key;
            #pragma unroll
            for (int q = KNN; q > 0; --q) {
                unsigned long long a = kv[q - 1], b = kv[q];
                kv[q - 1] = (a < b) ? a : b;
                kv[q]     = (a < b) ? b : a;
            }
        }
    }

    // 11-round warp merge; heads stay at kv[0]
    int nbr[KNN + 1];
    #pragma unroll
    for (int r = 0; r <= KNN; ++r) {
        unsigned long long mykey = kv[0];
        unsigned long long m = mykey;
        #pragma unroll
        for (int off = 16; off > 0; off >>= 1) {
            unsigned long long o = __shfl_xor_sync(0xFFFFFFFFu, m, off);
            m = (o < m) ? o : m;
        }
        nbr[r] = (int)(unsigned)(m & 0xFFFFFFFFull);
        if (mykey == m) {
            #pragma unroll
            for (int q = 0; q < KNN; ++q) kv[q] = kv[q + 1];
            kv[KNN] = 0xFFFFFFFFFFFFFFFFull;
        }
    }

    if (lane == 0) {
        float nx[KNN], ny[KNN], nz[KNN];
        float mx = 0.f, my = 0.f, mz = 0.f;
        #pragma unroll
        for (int k = 0; k < KNN; ++k) {
            int j = nbr[k + 1];
            nx[k] = sx[j]; ny[k] = sy[j]; nz[k] = sz[j];
            mx = FADD(mx, nx[k]); my = FADD(my, ny[k]); mz = FADD(mz, nz[k]);
        }
        mx = FDIV(mx, 10.f); my = FDIV(my, 10.f); mz = FDIV(mz, 10.f);

        float c00 = 0.f, c10 = 0.f, c20 = 0.f, c11 = 0.f, c21 = 0.f, c22 = 0.f;
        #pragma unroll
        for (int k = 0; k < KNN; ++k) {
            float cx = FSUB(nx[k], mx);
            float cy = FSUB(ny[k], my);
            float cz = FSUB(nz[k], mz);
            c00 = FADD(c00, FMUL(cx, cx));
            c10 = FADD(c10, FMUL(cy, cx));
            c20 = FADD(c20, FMUL(cz, cx));
            c11 = FADD(c11, FMUL(cy, cy));
            c21 = FADD(c21, FMUL(cz, cy));
            c22 = FADD(c22, FMUL(cz, cz));
        }
        c00 = FDIV(c00, 10.f); c10 = FDIV(c10, 10.f); c20 = FDIV(c20, 10.f);
        c11 = FDIV(c11, 10.f); c21 = FDIV(c21, 10.f); c22 = FDIV(c22, 10.f);

        float nrm[3];
        smallest_eigvec3(c00, c10, c20, c11, c21, c22, nrm);
        normals[i]            = nrm[0];
        normals[NPTS + i]     = nrm[1];
        normals[2 * NPTS + i] = nrm[2];
        normals[3 * NPTS + i] = nrm[0] * nrm[0] + nrm[1] * nrm[1] + nrm[2] * nrm[2];
    }
}

// ---------------------------------------------------------------------------
// Fast atan2 for y >= 0 (result in [0, pi]); cephes coefficients, ~1e-7 abs err
// ---------------------------------------------------------------------------
__device__ __forceinline__ float fast_atan2_pos(float y, float x) {
    const float PI    = 3.14159265358979323846f;
    const float PIO2  = 1.57079632679489661923f;
    const float PIO4  = 0.78539816339744830962f;
    const float TAN8  = 0.41421356237309504880f;

    float ax = fabsf(x);
    float mn = fminf(y, ax), mx = fmaxf(y, ax);
    float t = (mx == 0.f) ? 0.f : __fdividef(mn, mx);

    float add = 0.f;
    if (t > TAN8) { t = __fdividef(t - 1.f, t + 1.f); add = PIO4; }

    float z = t * t;
    float p = 8.05374449538e-2f;
    p = p * z - 1.38776856032e-1f;
    p = p * z + 1.99777106478e-1f;
    p = p * z - 3.33329491539e-1f;
    float r = fmaf(p * z, t, t) + add;

    if (y > ax)  r = PIO2 - r;
    if (x < 0.f) r = PI - r;
    return r;
}

// ---------------------------------------------------------------------------
// Kernel 2: PPF mean over j (block per point i) + 4->256 linear layer.
// Cross norms via ||a x b||^2 = |a|^2 |b|^2 - (a.b)^2 (clamped at 0).
// ---------------------------------------------------------------------------
__global__ void __launch_bounds__(256)
ppf_kernel(const float* __restrict__ pts, const float* __restrict__ normals,
           const float* __restrict__ W, const float* __restrict__ b,
           float* __restrict__ out) {
    __shared__ float sx[NPTS], sy[NPTS], sz[NPTS];
    __shared__ float red[32];
    int tid = threadIdx.x;
    for (int j = tid; j < NPTS; j += 256) {
        sx[j] = pts[j * 3 + 0];
        sy[j] = pts[j * 3 + 1];
        sz[j] = pts[j * 3 + 2];
    }
    __syncthreads();

    const float* gnx = normals;
    const float* gny = normals + NPTS;
    const float* gnz = normals + 2 * NPTS;
    const float* gns = normals + 3 * NPTS;

    int i = blockIdx.x;
    float pix = sx[i], piy = sy[i], piz = sz[i];
    float nix = __ldg(&gnx[i]), niy = __ldg(&gny[i]), niz = __ldg(&gnz[i]);
    float nisq = __ldg(&gns[i]);

    float s0 = 0.f, s1 = 0.f, s2 = 0.f, s3 = 0.f;
    #pragma unroll
    for (int jj = 0; jj < NPTS / 256; ++jj) {
        int j = tid + jj * 256;
        float dx = pix - sx[j], dy = piy - sy[j], dz = piz - sz[j];
        float njx = __ldg(&gnx[j]), njy = __ldg(&gny[j]), njz = __ldg(&gnz[j]);
        float njs = __ldg(&gns[j]);

        float sq = dx * dx + dy * dy + dz * dz;
        float dn = (sq > 0.f) ? sq * rsqrtf(sq) : 0.f;

        float dot1 = nix * dx + niy * dy + niz * dz;
        float csq1 = fmaf(nisq, sq, -(dot1 * dot1));
        float cn1  = (csq1 > 0.f) ? csq1 * rsqrtf(csq1) : 0.f;
        float a1 = fast_atan2_pos(cn1, dot1);

        float dot2 = njx * dx + njy * dy + njz * dz;
        float csq2 = fmaf(njs, sq, -(dot2 * dot2));
        float cn2  = (csq2 > 0.f) ? csq2 * rsqrtf(csq2) : 0.f;
        float a2 = fast_atan2_pos(cn2, dot2);

        float dot3 = nix * njx + niy * njy + niz * njz;
        float csq3 = fmaf(nisq, njs, -(dot3 * dot3));
        float cn3  = (csq3 > 0.f) ? csq3 * rsqrtf(csq3) : 0.f;
        float a3 = fast_atan2_pos(cn3, dot3);

        s0 += dn; s1 += a1; s2 += a2; s3 += a3;
    }

    #pragma unroll
    for (int off = 16; off > 0; off >>= 1) {
        s0 += __shfl_down_sync(0xFFFFFFFFu, s0, off);
        s1 += __shfl_down_sync(0xFFFFFFFFu, s1, off);
        s2 += __shfl_down_sync(0xFFFFFFFFu, s2, off);
        s3 += __shfl_down_sync(0xFFFFFFFFu, s3, off);
    }
    int w = tid >> 5, lane = tid & 31;
    if (lane == 0) {
        red[w * 4 + 0] = s0; red[w * 4 + 1] = s1;
        red[w * 4 + 2] = s2; red[w * 4 + 3] = s3;
    }
    __syncthreads();
    if (tid == 0) {
        float t0 = 0.f, t1 = 0.f, t2 = 0.f, t3 = 0.f;
        #pragma unroll
        for (int q = 0; q < 8; ++q) {
            t0 += red[q * 4 + 0]; t1 += red[q * 4 + 1];
            t2 += red[q * 4 + 2]; t3 += red[q * 4 + 3];
        }
        red[0] = t0 / 2048.f; red[1] = t1 / 2048.f;
        red[2] = t2 / 2048.f; red[3] = t3 / 2048.f;
    }
    __syncthreads();
    float f0 = red[0], f1 = red[1], f2 = red[2], f3 = red[3];

    float acc = f0 * W[tid * 4 + 0];
    acc = acc + f1 * W[tid * 4 + 1];
    acc = acc + f2 * W[tid * 4 + 2];
    acc = acc + f3 * W[tid * 4 + 3];
    acc = acc + b[tid];
    out[i * OUTF + tid] = acc;
}

extern "C" void kernel_launch(void* const* d_in, const int* in_sizes, int n_in,
                              void* d_out, int out_size) {
    const float* points = (const float*)d_in[0];   // (1, 2048, 3)
    const float* W      = (const float*)d_in[1];   // (256, 4)
    const float* b      = (const float*)d_in[2];   // (256,)
    float* out          = (float*)d_out;           // (1, 2048, 256)
    (void)in_sizes; (void)n_in; (void)out_size;

    float* normals;
    cudaGetSymbolAddress((void**)&normals, g_normals);

    knn_normals_kernel<<<NPTS / 8, 256>>>(points, normals);
    ppf_kernel<<<NPTS, 256>>>(points, normals, W, b, out);
}

// round 10
// speedup vs baseline: 9.4985x; 1.0637x over previous
#include <cuda_runtime.h>
#include <cuda_bf16.h>
#include <math.h>
#include <float.h>

#define NPTS 2048
#define KNN  10
#define OUTF 256
#define NTILES 64                 // 2048 / 32
#define NTPAIRS 2080              // 64*65/2

// _rn intrinsics: immune to compiler fast-math; used on all eigen/kNN-critical math
#define FMUL(a,b)  __fmul_rn((a),(b))
#define FADD(a,b)  __fadd_rn((a),(b))
#define FSUB(a,b)  __fsub_rn((a),(b))
#define FDIV(a,b)  __fdiv_rn((a),(b))
#define FSQRT(a)   __fsqrt_rn((a))

// SoA scratch: [0..N)=px [N..2N)=py [2N..3N)=pz [3N..4N)=nx [4N..5N)=ny
//              [5N..6N)=nz [6N..7N)=|n|^2
__device__ float  g_soa[NPTS * 7];
// per-(row, col-tile) partial PPF sums; single writer per slot (deterministic)
__device__ float4 g_part[NPTS * NTILES];

// ---------------------------------------------------------------------------
// LAPACK fp32 building blocks (netlib-faithful, LAPACK >= 3.10 conventions)
// ---------------------------------------------------------------------------

__device__ __forceinline__ float f_sign(float a, float b) {
    return (b >= 0.f) ? fabsf(a) : -fabsf(a);
}

__device__ __forceinline__ float slapy2f(float x, float y) {
    float xa = fabsf(x), ya = fabsf(y);
    float w = fmaxf(xa, ya), z = fminf(xa, ya);
    if (z == 0.f) return w;
    float t = FDIV(z, w);
    return FMUL(w, FSQRT(FADD(1.f, FMUL(t, t))));
}

__device__ __forceinline__ void slartgf(float f, float g, float* c, float* s, float* r) {
    if (g == 0.f)      { *c = 1.f; *s = 0.f; *r = f; }
    else if (f == 0.f) { *c = 0.f; *s = (g >= 0.f) ? 1.f : -1.f; *r = fabsf(g); }
    else {
        float d  = FSQRT(FADD(FMUL(f, f), FMUL(g, g)));
        float rr = (f >= 0.f) ? d : -d;
        *c = FDIV(fabsf(f), d);
        *s = FDIV(g, rr);
        *r = rr;
    }
}

__device__ void slaev2f(float a, float b, float c,
                        float* rt1, float* rt2, float* cs1, float* sn1) {
    float sm  = FADD(a, c);
    float df  = FSUB(a, c);
    float adf = fabsf(df);
    float tb  = FADD(b, b);
    float ab  = fabsf(tb);
    float acmx, acmn;
    if (fabsf(a) > fabsf(c)) { acmx = a; acmn = c; } else { acmx = c; acmn = a; }
    float rt;
    if (adf > ab) {
        float t = FDIV(ab, adf);
        rt = FMUL(adf, FSQRT(FADD(1.f, FMUL(t, t))));
    } else if (adf < ab) {
        float t = FDIV(adf, ab);
        rt = FMUL(ab, FSQRT(FADD(1.f, FMUL(t, t))));
    } else {
        rt = FMUL(ab, FSQRT(2.f));
    }
    int sgn1;
    if (sm < 0.f) {
        *rt1 = FMUL(0.5f, FSUB(sm, rt)); sgn1 = -1;
        *rt2 = FSUB(FMUL(FDIV(acmx, *rt1), acmn), FMUL(FDIV(b, *rt1), b));
    } else if (sm > 0.f) {
        *rt1 = FMUL(0.5f, FADD(sm, rt)); sgn1 = 1;
        *rt2 = FSUB(FMUL(FDIV(acmx, *rt1), acmn), FMUL(FDIV(b, *rt1), b));
    } else {
        *rt1 = FMUL(0.5f, rt); *rt2 = FMUL(-0.5f, rt); sgn1 = 1;
    }
    float cs; int sgn2;
    if (df >= 0.f) { cs = FADD(df, rt); sgn2 =  1; }
    else           { cs = FSUB(df, rt); sgn2 = -1; }
    float acs = fabsf(cs);
    if (acs > ab) {
        float ct = FDIV(-tb, cs);
        *sn1 = FDIV(1.f, FSQRT(FADD(1.f, FMUL(ct, ct))));
        *cs1 = FMUL(ct, *sn1);
    } else {
        if (ab == 0.f) { *cs1 = 1.f; *sn1 = 0.f; }
        else {
            float tn = FDIV(-cs, tb);
            *cs1 = FDIV(1.f, FSQRT(FADD(1.f, FMUL(tn, tn))));
            *sn1 = FMUL(tn, *cs1);
        }
    }
    if (sgn1 == sgn2) { float tn = *cs1; *cs1 = -(*sn1); *sn1 = tn; }
}

// ---------------------------------------------------------------------------
// ssteqr('I', n=3), register-resident (select-based accessors, no local mem).
// Control flow and arithmetic identical to netlib ssteqr.
// ---------------------------------------------------------------------------
__device__ void ssteqr3_reg(float& d0, float& d1, float& d2,
                            float& e0, float& e1,
                            float& za0, float& za1, float& za2,
                            float& zb0, float& zb1, float& zb2,
                            float& zc0, float& zc1, float& zc2) {
    const float eps    = 5.9604645e-8f;
    const float eps2   = eps * eps;
    const float safmin = 1.17549435e-38f;
    float wc0 = 0.f, wc1 = 0.f, ws0 = 0.f, ws1 = 0.f;

    auto dget = [&](int i) -> float { return i == 0 ? d0 : (i == 1 ? d1 : d2); };
    auto dset = [&](int i, float v) { if (i == 0) d0 = v; else if (i == 1) d1 = v; else d2 = v; };
    auto eget = [&](int i) -> float { return i == 0 ? e0 : e1; };
    auto eset = [&](int i, float v) { if (i == 0) e0 = v; else e1 = v; };
    auto wcget = [&](int i) -> float { return i == 0 ? wc0 : wc1; };
    auto wcset = [&](int i, float v) { if (i == 0) wc0 = v; else wc1 = v; };
    auto wsget = [&](int i) -> float { return i == 0 ? ws0 : ws1; };
    auto wsset = [&](int i, float v) { if (i == 0) ws0 = v; else ws1 = v; };

    auto rot = [&](int cb1, float c, float s) {
        if (cb1 == 1) {
            float t;
            t = zb0; zb0 = FSUB(FMUL(c, t), FMUL(s, za0)); za0 = FADD(FMUL(s, t), FMUL(c, za0));
            t = zb1; zb1 = FSUB(FMUL(c, t), FMUL(s, za1)); za1 = FADD(FMUL(s, t), FMUL(c, za1));
            t = zb2; zb2 = FSUB(FMUL(c, t), FMUL(s, za2)); za2 = FADD(FMUL(s, t), FMUL(c, za2));
        } else {
            float t;
            t = zc0; zc0 = FSUB(FMUL(c, t), FMUL(s, zb0)); zb0 = FADD(FMUL(s, t), FMUL(c, zb0));
            t = zc1; zc1 = FSUB(FMUL(c, t), FMUL(s, zb1)); zb1 = FADD(FMUL(s, t), FMUL(c, zb1));
            t = zc2; zc2 = FSUB(FMUL(c, t), FMUL(s, zb2)); zb2 = FADD(FMUL(s, t), FMUL(c, zb2));
        }
    };
    auto slasr_bL = [&](int lcol, int mm) {
        for (int j = mm - 1; j >= 1; --j) {
            float c = wcget(lcol - 2 + j), s = wsget(lcol - 2 + j);
            if (c != 1.f || s != 0.f) rot(lcol + j - 1, c, s);
        }
    };
    auto slasr_fL = [&](int lcol, int mm) {
        for (int j = 1; j <= mm - 1; ++j) {
            float c = wcget(lcol - 2 + j), s = wsget(lcol - 2 + j);
            if (c != 1.f || s != 0.f) rot(lcol + j - 1, c, s);
        }
    };

    int l1, l, lsv, lend, lendsv, m, i, jtot, nmaxit;
    float p, g, r, s, c, f, bb, rt1, rt2, anorm, tst;
    nmaxit = 90; jtot = 0; l1 = 1;

L10:
    if (l1 > 3) goto L160;
    if (l1 > 1) eset(l1 - 2, 0.f);
    if (l1 <= 2) {
        for (m = l1; m <= 2; ++m) {
            tst = fabsf(eget(m - 1));
            if (tst == 0.f) goto L30;
            if (tst <= FMUL(FMUL(FSQRT(fabsf(dget(m - 1))), FSQRT(fabsf(dget(m)))), eps)) {
                eset(m - 1, 0.f); goto L30;
            }
        }
    }
    m = 3;
L30:
    l = l1; lsv = l; lend = m; lendsv = lend; l1 = m + 1;
    if (lend == l) goto L10;
    anorm = 0.f;
    for (i = l; i <= lend; ++i)     anorm = fmaxf(anorm, fabsf(dget(i - 1)));
    for (i = l; i <= lend - 1; ++i) anorm = fmaxf(anorm, fabsf(eget(i - 1)));
    if (anorm == 0.f) goto L10;
    if (fabsf(dget(lend - 1)) < fabsf(dget(l - 1))) { lend = lsv; l = lendsv; }
    if (lend > l) goto L40; else goto L90;

L40: // QL
    if (l != lend) {
        for (m = l; m <= lend - 1; ++m) {
            tst = FMUL(eget(m - 1), eget(m - 1));
            if (tst <= FADD(FMUL(FMUL(eps2, fabsf(dget(m - 1))), fabsf(dget(m))), safmin)) goto L60;
        }
    }
    m = lend;
L60:
    if (m < lend) eset(m - 1, 0.f);
    p = dget(l - 1);
    if (m == l) goto L80;
    if (m == l + 1) {
        slaev2f(dget(l - 1), eget(l - 1), dget(l), &rt1, &rt2, &c, &s);
        wcset(l - 1, c); wsset(l - 1, s);
        slasr_bL(l, 2);
        dset(l - 1, rt1); dset(l, rt2); eset(l - 1, 0.f);
        l += 2;
        if (l <= lend) goto L40;
        goto L140;
    }
    if (jtot == nmaxit) goto L140;
    jtot++;
    g = FDIV(FSUB(dget(l), p), FMUL(2.f, eget(l - 1)));
    r = slapy2f(g, 1.f);
    g = FADD(FSUB(dget(m - 1), p), FDIV(eget(l - 1), FADD(g, f_sign(r, g))));
    s = 1.f; c = 1.f; p = 0.f;
    for (i = m - 1; i >= l; --i) {
        f  = FMUL(s, eget(i - 1));
        bb = FMUL(c, eget(i - 1));
        slartgf(g, f, &c, &s, &r);
        if (i != m - 1) eset(i, r);
        g = FSUB(dget(i), p);
        r = FADD(FMUL(FSUB(dget(i - 1), g), s), FMUL(FMUL(2.f, c), bb));
        p = FMUL(s, r);
        dset(i, FADD(g, p));
        g = FSUB(FMUL(c, r), bb);
        wcset(i - 1, c); wsset(i - 1, -s);
    }
    slasr_bL(l, m - l + 1);
    dset(l - 1, FSUB(dget(l - 1), p));
    eset(l - 1, g);
    goto L40;
L80:
    dset(l - 1, p);
    l++;
    if (l <= lend) goto L40;
    goto L140;

L90: // QR
    if (l != lend) {
        for (m = l; m >= lend + 1; --m) {
            tst = FMUL(eget(m - 2), eget(m - 2));
            if (tst <= FADD(FMUL(FMUL(eps2, fabsf(dget(m - 1))), fabsf(dget(m - 2))), safmin)) goto L110;
        }
    }
    m = lend;
L110:
    if (m > lend) eset(m - 2, 0.f);
    p = dget(l - 1);
    if (m == l) goto L130;
    if (m == l - 1) {
        slaev2f(dget(l - 2), eget(l - 2), dget(l - 1), &rt1, &rt2, &c, &s);
        wcset(m - 1, c); wsset(m - 1, s);
        slasr_fL(l - 1, 2);
        dset(l - 2, rt1); dset(l - 1, rt2); eset(l - 2, 0.f);
        l -= 2;
        if (l >= lend) goto L90;
        goto L140;
    }
    if (jtot == nmaxit) goto L140;
    jtot++;
    g = FDIV(FSUB(dget(l - 2), p), FMUL(2.f, eget(l - 2)));
    r = slapy2f(g, 1.f);
    g = FADD(FSUB(dget(m - 1), p), FDIV(eget(l - 2), FADD(g, f_sign(r, g))));
    s = 1.f; c = 1.f; p = 0.f;
    for (i = m; i <= l - 1; ++i) {
        f  = FMUL(s, eget(i - 1));
        bb = FMUL(c, eget(i - 1));
        slartgf(g, f, &c, &s, &r);
        if (i != m) eset(i - 2, r);
        g = FSUB(dget(i - 1), p);
        r = FADD(FMUL(FSUB(dget(i), g), s), FMUL(FMUL(2.f, c), bb));
        p = FMUL(s, r);
        dset(i - 1, FADD(g, p));
        g = FSUB(FMUL(c, r), bb);
        wcset(i - 1, c); wsset(i - 1, s);
    }
    slasr_fL(m, l - m + 1);
    dset(l - 1, FSUB(dget(l - 1), p));
    eset(l - 2, g);
    goto L90;
L130:
    dset(l - 1, p);
    l--;
    if (l >= lend) goto L90;
    goto L140;

L140:
    if (jtot < nmaxit) goto L10;
    goto L160;

L160:
    {
        auto swapcol = [&](int c1, int c2) {
            float t;
            if (c1 == 0 && c2 == 1) {
                t = za0; za0 = zb0; zb0 = t;
                t = za1; za1 = zb1; zb1 = t;
                t = za2; za2 = zb2; zb2 = t;
            } else if (c1 == 0) {
                t = za0; za0 = zc0; zc0 = t;
                t = za1; za1 = zc1; zc1 = t;
                t = za2; za2 = zc2; zc2 = t;
            } else {
                t = zb0; zb0 = zc0; zc0 = t;
                t = zb1; zb1 = zc1; zc1 = t;
                t = zb2; zb2 = zc2; zc2 = t;
            }
        };
        for (int ii = 2; ii <= 3; ++ii) {
            int ia = ii - 1, k = ia;
            float pp = dget(ia - 1);
            for (int j = ii; j <= 3; ++j)
                if (dget(j - 1) < pp) { k = j; pp = dget(j - 1); }
            if (k != ia) {
                dset(k - 1, dget(ia - 1)); dset(ia - 1, pp);
                swapcol(ia - 1, k - 1);
            }
        }
    }
}

__device__ void smallest_eigvec3(float a11, float a21, float a31,
                                 float a22, float a32, float a33,
                                 float* nrm) {
    float alpha = a21;
    float xnorm = fabsf(a31);
    float tau1, v3, eh;
    if (xnorm == 0.f) {
        tau1 = 0.f; eh = alpha; v3 = 0.f;
    } else {
        float beta = -f_sign(slapy2f(alpha, xnorm), alpha);
        tau1 = FDIV(FSUB(beta, alpha), beta);
        v3   = FMUL(a31, FDIV(1.f, FSUB(alpha, beta)));
        eh   = beta;
    }
    if (tau1 != 0.f) {
        float x1 = FMUL(tau1, FADD(a22, FMUL(a32, v3)));
        float x2 = FMUL(tau1, FADD(a32, FMUL(a33, v3)));
        float al = FMUL(FMUL(-0.5f, tau1), FADD(x1, FMUL(x2, v3)));
        float w1 = FADD(x1, al);
        float w2 = FADD(x2, FMUL(al, v3));
        a22 = FSUB(a22, FMUL(2.f, w1));
        a32 = FSUB(a32, FADD(FMUL(v3, w1), w2));
        a33 = FSUB(a33, FMUL(2.f, FMUL(v3, w2)));
    }
    float d0 = a11, d1 = a22, d2 = a33;
    float e0 = eh, e1 = a32;
    float za0 = 1.f, za1 = 0.f, za2 = 0.f;
    float zb0 = 0.f, zb1 = 1.f, zb2 = 0.f;
    float zc0 = 0.f, zc1 = 0.f, zc2 = 1.f;

    ssteqr3_reg(d0, d1, d2, e0, e1,
                za0, za1, za2, zb0, zb1, zb2, zc0, zc1, zc2);

    float z0 = za0, z1 = za1, z2 = za2;
    if (tau1 != 0.f) {
        float t = FMUL(tau1, FADD(z1, FMUL(v3, z2)));
        z1 = FSUB(z1, t);
        z2 = FSUB(z2, FMUL(t, v3));
    }
    nrm[0] = z0; nrm[1] = z1; nrm[2] = z2;
}

// ---------------------------------------------------------------------------
// Kernel 1: warp-per-point kNN (register top-11, packed u64 keys == top_k's
// stable (sq, idx) order) + covariance + smallest eigenvector (lane 0).
// Also emits the points + normals SoA used by the symmetric PPF kernel.
// ---------------------------------------------------------------------------
__global__ void __launch_bounds__(256)
knn_normals_kernel(const float* __restrict__ pts, float* __restrict__ soa) {
    __shared__ float sx[NPTS], sy[NPTS], sz[NPTS];
    int tid = threadIdx.x;
    for (int j = tid; j < NPTS; j += 256) {
        sx[j] = pts[j * 3 + 0];
        sy[j] = pts[j * 3 + 1];
        sz[j] = pts[j * 3 + 2];
    }
    __syncthreads();

    int warp = tid >> 5, lane = tid & 31;
    int i = blockIdx.x * 8 + warp;

    float pix = sx[i], piy = sy[i], piz = sz[i];

    unsigned long long kv[KNN + 1];
    #pragma unroll
    for (int q = 0; q <= KNN; ++q) kv[q] = 0xFFFFFFFFFFFFFFFFull;

    #pragma unroll 4
    for (int j = lane; j < NPTS; j += 32) {
        float dx = FSUB(pix, sx[j]);
        float dy = FSUB(piy, sy[j]);
        float dz = FSUB(piz, sz[j]);
        float sq = FADD(FADD(FMUL(dx, dx), FMUL(dy, dy)), FMUL(dz, dz));
        unsigned long long key =
            ((unsigned long long)__float_as_uint(sq) << 32) | (unsigned)j;
        if (key < kv[KNN]) {
            kv[KNN] = key;
            #pragma unroll
            for (int q = KNN; q > 0; --q) {
                unsigned long long a = kv[q - 1], b = kv[q];
                kv[q - 1] = (a < b) ? a : b;
                kv[q]     = (a < b) ? b : a;
            }
        }
    }

    int nbr[KNN + 1];
    #pragma unroll
    for (int r = 0; r <= KNN; ++r) {
        unsigned long long mykey = kv[0];
        unsigned long long m = mykey;
        #pragma unroll
        for (int off = 16; off > 0; off >>= 1) {
            unsigned long long o = __shfl_xor_sync(0xFFFFFFFFu, m, off);
            m = (o < m) ? o : m;
        }
        nbr[r] = (int)(unsigned)(m & 0xFFFFFFFFull);
        if (mykey == m) {
            #pragma unroll
            for (int q = 0; q < KNN; ++q) kv[q] = kv[q + 1];
            kv[KNN] = 0xFFFFFFFFFFFFFFFFull;
        }
    }

    if (lane == 0) {
        float nx[KNN], ny[KNN], nz[KNN];
        float mx = 0.f, my = 0.f, mz = 0.f;
        #pragma unroll
        for (int k = 0; k < KNN; ++k) {
            int j = nbr[k + 1];
            nx[k] = sx[j]; ny[k] = sy[j]; nz[k] = sz[j];
            mx = FADD(mx, nx[k]); my = FADD(my, ny[k]); mz = FADD(mz, nz[k]);
        }
        mx = FDIV(mx, 10.f); my = FDIV(my, 10.f); mz = FDIV(mz, 10.f);

        float c00 = 0.f, c10 = 0.f, c20 = 0.f, c11 = 0.f, c21 = 0.f, c22 = 0.f;
        #pragma unroll
        for (int k = 0; k < KNN; ++k) {
            float cx = FSUB(nx[k], mx);
            float cy = FSUB(ny[k], my);
            float cz = FSUB(nz[k], mz);
            c00 = FADD(c00, FMUL(cx, cx));
            c10 = FADD(c10, FMUL(cy, cx));
            c20 = FADD(c20, FMUL(cz, cx));
            c11 = FADD(c11, FMUL(cy, cy));
            c21 = FADD(c21, FMUL(cz, cy));
            c22 = FADD(c22, FMUL(cz, cz));
        }
        c00 = FDIV(c00, 10.f); c10 = FDIV(c10, 10.f); c20 = FDIV(c20, 10.f);
        c11 = FDIV(c11, 10.f); c21 = FDIV(c21, 10.f); c22 = FDIV(c22, 10.f);

        float nrm[3];
        smallest_eigvec3(c00, c10, c20, c11, c21, c22, nrm);
        soa[i]            = pix;
        soa[NPTS + i]     = piy;
        soa[2 * NPTS + i] = piz;
        soa[3 * NPTS + i] = nrm[0];
        soa[4 * NPTS + i] = nrm[1];
        soa[5 * NPTS + i] = nrm[2];
        soa[6 * NPTS + i] = nrm[0] * nrm[0] + nrm[1] * nrm[1] + nrm[2] * nrm[2];
    }
}

// ---------------------------------------------------------------------------
// Fast atan2 for y >= 0 (result in [0, pi]); cephes coefficients, ~1e-7 abs err
// ---------------------------------------------------------------------------
__device__ __forceinline__ float fast_atan2_pos(float y, float x) {
    const float PI    = 3.14159265358979323846f;
    const float PIO2  = 1.57079632679489661923f;
    const float PIO4  = 0.78539816339744830962f;
    const float TAN8  = 0.41421356237309504880f;

    float ax = fabsf(x);
    float mn = fminf(y, ax), mx = fmaxf(y, ax);
    float t = (mx == 0.f) ? 0.f : __fdividef(mn, mx);

    float add = 0.f;
    if (t > TAN8) { t = __fdividef(t - 1.f, t + 1.f); add = PIO4; }

    float z = t * t;
    float p = 8.05374449538e-2f;
    p = p * z - 1.38776856032e-1f;
    p = p * z + 1.99777106478e-1f;
    p = p * z - 3.33329491539e-1f;
    float r = fmaf(p * z, t, t) + add;

    if (y > ax)  r = PIO2 - r;
    if (x < 0.f) r = PI - r;
    return r;
}

// compute PPF features for ordered pair given i-data and j-data
__device__ __forceinline__ void ppf_pair(
    float pix, float piy, float piz, float nix, float niy, float niz, float nis,
    float pjx, float pjy, float pjz, float njx, float njy, float njz, float njs,
    float& dn, float& a1, float& a2, float& a3)
{
    float dx = pix - pjx, dy = piy - pjy, dz = piz - pjz;
    float sq = dx * dx + dy * dy + dz * dz;
    dn = (sq > 0.f) ? sq * rsqrtf(sq) : 0.f;

    float dot1 = nix * dx + niy * dy + niz * dz;
    float csq1 = fmaf(nis, sq, -(dot1 * dot1));
    float cn1  = (csq1 > 0.f) ? csq1 * rsqrtf(csq1) : 0.f;
    a1 = fast_atan2_pos(cn1, dot1);

    float dot2 = njx * dx + njy * dy + njz * dz;
    float csq2 = fmaf(njs, sq, -(dot2 * dot2));
    float cn2  = (csq2 > 0.f) ? csq2 * rsqrtf(csq2) : 0.f;
    a2 = fast_atan2_pos(cn2, dot2);

    float dot3 = nix * njx + niy * njy + niz * njz;
    float csq3 = fmaf(nis, njs, -(dot3 * dot3));
    float cn3  = (csq3 > 0.f) ? csq3 * rsqrtf(csq3) : 0.f;
    a3 = fast_atan2_pos(cn3, dot3);
}

// ---------------------------------------------------------------------------
// Kernel 2: symmetric PPF. One warp per unordered 32x32 tile pair (B <= A).
// F(j,i) = [dn, pi - a2(i,j), pi - a1(i,j), a3]  (exact identity).
// Each (row, col-tile) partial-sum slot has exactly one writer.
// ---------------------------------------------------------------------------
__global__ void __launch_bounds__(128)
sym_ppf_kernel(const float* __restrict__ soa, float4* __restrict__ part) {
    const float PI = 3.14159265358979323846f;
    int wt = blockIdx.x * 4 + (threadIdx.x >> 5);
    if (wt >= NTPAIRS) return;
    int lane = threadIdx.x & 31;

    // decode wt -> (A, B) with 0 <= B <= A < 64, wt = A(A+1)/2 + B
    int A = (int)((sqrtf(8.f * (float)wt + 1.f) - 1.f) * 0.5f);
    while ((A + 1) * (A + 2) / 2 <= wt) ++A;
    while (A * (A + 1) / 2 > wt) --A;
    int B = wt - A * (A + 1) / 2;

    const float* px = soa;
    const float* py = soa + NPTS;
    const float* pz = soa + 2 * NPTS;
    const float* nx = soa + 3 * NPTS;
    const float* ny = soa + 4 * NPTS;
    const float* nz = soa + 5 * NPTS;
    const float* ns = soa + 6 * NPTS;

    int ri = B * 32 + lane;      // i-row owned by this lane
    int rj = A * 32 + lane;      // j-row owned by this lane
    float pix = __ldg(&px[ri]), piy = __ldg(&py[ri]), piz = __ldg(&pz[ri]);
    float nix = __ldg(&nx[ri]), niy = __ldg(&ny[ri]), niz = __ldg(&nz[ri]);
    float nis = __ldg(&ns[ri]);
    float qjx = __ldg(&px[rj]), qjy = __ldg(&py[rj]), qjz = __ldg(&pz[rj]);
    float mjx = __ldg(&nx[rj]), mjy = __ldg(&ny[rj]), mjz = __ldg(&nz[rj]);
    float mjs = __ldg(&ns[rj]);

    float ai0 = 0.f, ai1 = 0.f, ai2 = 0.f, ai3 = 0.f;   // row ri partial sums
    float aj0 = 0.f, aj1 = 0.f, aj2 = 0.f, aj3 = 0.f;   // row rj partial sums

    if (A != B) {
        #pragma unroll 4
        for (int s = 0; s < 32; ++s) {
            int src = (lane + s) & 31;
            float pjx = __shfl_sync(0xFFFFFFFFu, qjx, src);
            float pjy = __shfl_sync(0xFFFFFFFFu, qjy, src);
            float pjz = __shfl_sync(0xFFFFFFFFu, qjz, src);
            float njx = __shfl_sync(0xFFFFFFFFu, mjx, src);
            float njy = __shfl_sync(0xFFFFFFFFu, mjy, src);
            float njz = __shfl_sync(0xFFFFFFFFu, mjz, src);
            float njs = __shfl_sync(0xFFFFFFFFu, mjs, src);

            float dn, a1, a2, a3;
            ppf_pair(pix, piy, piz, nix, niy, niz, nis,
                     pjx, pjy, pjz, njx, njy, njz, njs, dn, a1, a2, a3);

            ai0 += dn; ai1 += a1; ai2 += a2; ai3 += a3;

            // contribution to row rj' = A*32+src, owner lane = src.
            // owner o receives from lane (o - s) & 31.
            float c0 = dn, c1 = PI - a2, c2 = PI - a1, c3 = a3;
            int rsrc = (lane - s) & 31;
            aj0 += __shfl_sync(0xFFFFFFFFu, c0, rsrc);
            aj1 += __shfl_sync(0xFFFFFFFFu, c1, rsrc);
            aj2 += __shfl_sync(0xFFFFFFFFu, c2, rsrc);
            aj3 += __shfl_sync(0xFFFFFFFFu, c3, rsrc);
        }
        part[ri * NTILES + A] = make_float4(ai0, ai1, ai2, ai3);
        part[rj * NTILES + B] = make_float4(aj0, aj1, aj2, aj3);
    } else {
        // diagonal tile: all 32x32 ordered pairs directly (self-pair gives 0s)
        #pragma unroll 4
        for (int s = 0; s < 32; ++s) {
            int src = (lane + s) & 31;
            float pjx = __shfl_sync(0xFFFFFFFFu, qjx, src);
            float pjy = __shfl_sync(0xFFFFFFFFu, qjy, src);
            float pjz = __shfl_sync(0xFFFFFFFFu, qjz, src);
            float njx = __shfl_sync(0xFFFFFFFFu, mjx, src);
            float njy = __shfl_sync(0xFFFFFFFFu, mjy, src);
            float njz = __shfl_sync(0xFFFFFFFFu, mjz, src);
            float njs = __shfl_sync(0xFFFFFFFFu, mjs, src);

            float dn, a1, a2, a3;
            ppf_pair(pix, piy, piz, nix, niy, niz, nis,
                     pjx, pjy, pjz, njx, njy, njz, njs, dn, a1, a2, a3);

            ai0 += dn; ai1 += a1; ai2 += a2; ai3 += a3;
        }
        part[ri * NTILES + A] = make_float4(ai0, ai1, ai2, ai3);
    }
}

// ---------------------------------------------------------------------------
// Kernel 3: reduce 64 partials per row (fixed order) + 4->256 linear layer
// ---------------------------------------------------------------------------
__global__ void __launch_bounds__(256)
finalize_kernel(const float4* __restrict__ part,
                const float* __restrict__ W, const float* __restrict__ b,
                float* __restrict__ out) {
    __shared__ float4 sf[NTILES];
    __shared__ float feat[4];
    int i = blockIdx.x, t = threadIdx.x;
    if (t < NTILES) sf[t] = part[i * NTILES + t];
    __syncthreads();
    if (t == 0) {
        float s0 = 0.f, s1 = 0.f, s2 = 0.f, s3 = 0.f;
        #pragma unroll
        for (int q = 0; q < NTILES; ++q) {
            float4 v = sf[q];
            s0 += v.x; s1 += v.y; s2 += v.z; s3 += v.w;
        }
        feat[0] = s0 / 2048.f; feat[1] = s1 / 2048.f;
        feat[2] = s2 / 2048.f; feat[3] = s3 / 2048.f;
    }
    __syncthreads();
    float f0 = feat[0], f1 = feat[1], f2 = feat[2], f3 = feat[3];
    float acc = f0 * W[t * 4 + 0];
    acc = acc + f1 * W[t * 4 + 1];
    acc = acc + f2 * W[t * 4 + 2];
    acc = acc + f3 * W[t * 4 + 3];
    acc = acc + b[t];
    out[i * OUTF + t] = acc;
}

extern "C" void kernel_launch(void* const* d_in, const int* in_sizes, int n_in,
                              void* d_out, int out_size) {
    const float* points = (const float*)d_in[0];   // (1, 2048, 3)
    const float* W      = (const float*)d_in[1];   // (256, 4)
    const float* b      = (const float*)d_in[2];   // (256,)
    float* out          = (float*)d_out;           // (1, 2048, 256)
    (void)in_sizes; (void)n_in; (void)out_size;

    float* soa;
    float4* part;
    cudaGetSymbolAddress((void**)&soa, g_soa);
    cudaGetSymbolAddress((void**)&part, g_part);

    knn_normals_kernel<<<NPTS / 8, 256>>>(points, soa);
    sym_ppf_kernel<<<(NTPAIRS + 3) / 4, 128>>>(soa, part);
    finalize_kernel<<<NPTS, 256>>>(part, W, b, out);
}